// round 1
// baseline (speedup 1.0000x reference)
#include <cuda_runtime.h>
#include <math.h>

#define T_SEQ 2048
#define BATCH 2
#define NHEAD 16
#define HDIM 64
#define DMODEL 1024

// Scratch (allocation-free rule: __device__ globals)
__device__ float g_qkv[BATCH * T_SEQ * 3 * DMODEL];   // [B*T, 3*D], 48 MB
__device__ float g_attn[BATCH * T_SEQ * DMODEL];      // [B*T, D], 16 MB

// ---------------------------------------------------------------------------
// Classic 128x128x16 shared-memory SGEMM with bias: C[M,N] = A[M,K]*B[K,N]+bias
// M,N,K all multiples of tile sizes for this problem (no bounds checks).
// ---------------------------------------------------------------------------
__global__ __launch_bounds__(256) void sgemm_bias(
    const float* __restrict__ A, const float* __restrict__ B,
    const float* __restrict__ bias, float* __restrict__ C,
    int M, int N, int K)
{
    const int BK = 16;
    __shared__ float As[BK][128];
    __shared__ float Bs[BK][128];

    int tid = threadIdx.x;
    int bm = blockIdx.y * 128;
    int bn = blockIdx.x * 128;
    int ty = tid >> 4;       // 0..15
    int tx = tid & 15;       // 0..15

    int arow = tid >> 2;            // 0..63
    int acol = (tid & 3) * 4;       // 0,4,8,12
    int brow = tid >> 5;            // 0..7
    int bcol = (tid & 31) * 4;      // 0..124

    float acc[8][8] = {};

    for (int k0 = 0; k0 < K; k0 += BK) {
#pragma unroll
        for (int r = 0; r < 2; r++) {
            int rr = arow + r * 64;
            float4 av = *(const float4*)(A + (size_t)(bm + rr) * K + k0 + acol);
            As[acol + 0][rr] = av.x;
            As[acol + 1][rr] = av.y;
            As[acol + 2][rr] = av.z;
            As[acol + 3][rr] = av.w;
        }
#pragma unroll
        for (int r = 0; r < 2; r++) {
            int rr = brow + r * 8;
            *(float4*)&Bs[rr][bcol] = *(const float4*)(B + (size_t)(k0 + rr) * N + bn + bcol);
        }
        __syncthreads();
#pragma unroll
        for (int kk = 0; kk < BK; kk++) {
            float ar[8], br[8];
#pragma unroll
            for (int i = 0; i < 8; i++) ar[i] = As[kk][ty * 8 + i];
#pragma unroll
            for (int j = 0; j < 8; j++) br[j] = Bs[kk][tx * 8 + j];
#pragma unroll
            for (int i = 0; i < 8; i++)
#pragma unroll
                for (int j = 0; j < 8; j++)
                    acc[i][j] += ar[i] * br[j];
        }
        __syncthreads();
    }

#pragma unroll
    for (int i = 0; i < 8; i++) {
        int row = bm + ty * 8 + i;
#pragma unroll
        for (int j = 0; j < 8; j += 4) {
            int col = bn + tx * 8 + j;
            float4 o;
            o.x = acc[i][j + 0] + bias[col + 0];
            o.y = acc[i][j + 1] + bias[col + 1];
            o.z = acc[i][j + 2] + bias[col + 2];
            o.w = acc[i][j + 3] + bias[col + 3];
            *(float4*)(C + (size_t)row * N + col) = o;
        }
    }
}

// ---------------------------------------------------------------------------
// RoPE exactly matching the reference's scrambled indexing:
//   rope = concat(sin(freqs), cos(freqs))  (len 64)
//   sinv[j] = rope[2j], cosv[j] = rope[2j+1]
//   out[j]    = x[2j]*cosv[j] - x[2j+1]*sinv[j]
//   out[32+j] = x[2j]*sinv[j] + x[2j+1]*cosv[j]
// One thread per (b, t, h); applies to q and k in-place in g_qkv.
// ---------------------------------------------------------------------------
__device__ __forceinline__ float invfreq(int i) {
    // 10000^(-i/32)
    return exp2f(-(float)i * (13.287712379549449f / 32.0f));  // log2(10000)=13.2877...
}

__device__ __forceinline__ float rope_val(float tf, int i) {
    if (i < 32) return sinf(tf * invfreq(i));
    return cosf(tf * invfreq(i - 32));
}

__global__ void rope_kernel()
{
    int idx = blockIdx.x * blockDim.x + threadIdx.x;   // over B*T*H
    int h = idx % NHEAD;
    int t = (idx / NHEAD) % T_SEQ;
    int b = idx / (NHEAD * T_SEQ);
    float tf = (float)t;

    float sv[32], cv[32];
#pragma unroll
    for (int j = 0; j < 32; j++) {
        sv[j] = rope_val(tf, 2 * j);
        cv[j] = rope_val(tf, 2 * j + 1);
    }

    float* base = g_qkv + ((size_t)(b * T_SEQ + t)) * (3 * DMODEL) + h * HDIM;
#pragma unroll
    for (int s = 0; s < 2; s++) {            // q then k
        float* p = base + s * DMODEL;
        float x[64];
#pragma unroll
        for (int d = 0; d < 64; d += 4) {
            float4 v = *(const float4*)(p + d);
            x[d] = v.x; x[d + 1] = v.y; x[d + 2] = v.z; x[d + 3] = v.w;
        }
        float o[64];
#pragma unroll
        for (int j = 0; j < 32; j++) {
            o[j]      = x[2 * j] * cv[j] - x[2 * j + 1] * sv[j];
            o[32 + j] = x[2 * j] * sv[j] + x[2 * j + 1] * cv[j];
        }
#pragma unroll
        for (int d = 0; d < 64; d += 4) {
            float4 v; v.x = o[d]; v.y = o[d + 1]; v.z = o[d + 2]; v.w = o[d + 3];
            *(float4*)(p + d) = v;
        }
    }
}

// ---------------------------------------------------------------------------
// Flash attention (fp32, online softmax). One query per thread, 128 q/block,
// 32-key tiles staged through shared memory (broadcast reads).
// Writes attention output directly in [B*T, D] layout (head-interleaved).
// ---------------------------------------------------------------------------
__global__ __launch_bounds__(128) void flash_kernel()
{
    int qt = blockIdx.x;       // q tile (128 queries)
    int h  = blockIdx.y;
    int b  = blockIdx.z;
    int qi = qt * 128 + threadIdx.x;

    __shared__ float Ks[32][64];
    __shared__ float Vs[32][64];

    const float scale = 0.125f;   // HD^-0.5 = 1/8

    float q[64], acc[64];
    const float* qrow = g_qkv + ((size_t)(b * T_SEQ + qi)) * (3 * DMODEL) + h * HDIM;
#pragma unroll
    for (int d = 0; d < 64; d += 4) {
        float4 v = *(const float4*)(qrow + d);
        q[d] = v.x * scale; q[d + 1] = v.y * scale;
        q[d + 2] = v.z * scale; q[d + 3] = v.w * scale;
        acc[d] = 0.f; acc[d + 1] = 0.f; acc[d + 2] = 0.f; acc[d + 3] = 0.f;
    }

    float m = -INFINITY, l = 0.f;

    int row = threadIdx.x >> 2;            // 0..31
    int cg  = (threadIdx.x & 3) * 16;      // 0,16,32,48

    int ktiles = qt * 4 + 4;               // covers keys up to q0+127
    for (int kt = 0; kt < ktiles; kt++) {
        int k0 = kt * 32;
        const float* krow = g_qkv + ((size_t)(b * T_SEQ + k0 + row)) * (3 * DMODEL)
                            + DMODEL + h * HDIM + cg;
        const float* vrow = krow + DMODEL;
        __syncthreads();
#pragma unroll
        for (int u = 0; u < 16; u += 4) {
            *(float4*)&Ks[row][cg + u] = *(const float4*)(krow + u);
            *(float4*)&Vs[row][cg + u] = *(const float4*)(vrow + u);
        }
        __syncthreads();

        float s[32];
        float mt = -INFINITY;
#pragma unroll
        for (int j = 0; j < 32; j++) {
            float a = 0.f;
#pragma unroll
            for (int d = 0; d < 64; d += 4) {
                float4 kv = *(const float4*)&Ks[j][d];
                a += q[d] * kv.x + q[d + 1] * kv.y + q[d + 2] * kv.z + q[d + 3] * kv.w;
            }
            s[j] = (k0 + j <= qi) ? a : -INFINITY;
            mt = fmaxf(mt, s[j]);
        }
        float mn = fmaxf(m, mt);
        float alpha = __expf(m - mn);   // exp(-inf - finite) -> 0 on first tile
        l *= alpha;
#pragma unroll
        for (int d = 0; d < 64; d++) acc[d] *= alpha;
        m = mn;
#pragma unroll
        for (int j = 0; j < 32; j++) {
            float p = __expf(s[j] - m);
            l += p;
#pragma unroll
            for (int d = 0; d < 64; d += 4) {
                float4 vv = *(const float4*)&Vs[j][d];
                acc[d]     += p * vv.x;
                acc[d + 1] += p * vv.y;
                acc[d + 2] += p * vv.z;
                acc[d + 3] += p * vv.w;
            }
        }
    }

    float inv_l = 1.f / l;
    float* orow = g_attn + ((size_t)(b * T_SEQ + qi)) * DMODEL + h * HDIM;
#pragma unroll
    for (int d = 0; d < 64; d += 4) {
        float4 o;
        o.x = acc[d] * inv_l; o.y = acc[d + 1] * inv_l;
        o.z = acc[d + 2] * inv_l; o.w = acc[d + 3] * inv_l;
        *(float4*)(orow + d) = o;
    }
}

// ---------------------------------------------------------------------------
extern "C" void kernel_launch(void* const* d_in, const int* in_sizes, int n_in,
                              void* d_out, int out_size)
{
    const float* x      = (const float*)d_in[0];
    const float* qkv_w  = (const float*)d_in[1];
    const float* qkv_b  = (const float*)d_in[2];
    const float* out_w  = (const float*)d_in[3];
    const float* out_b  = (const float*)d_in[4];
    float* out = (float*)d_out;

    float *qkv_buf, *attn_buf;
    cudaGetSymbolAddress((void**)&qkv_buf, g_qkv);
    cudaGetSymbolAddress((void**)&attn_buf, g_attn);

    const int M = BATCH * T_SEQ;   // 4096

    // 1) QKV GEMM + bias: [4096,1024] x [1024,3072]
    sgemm_bias<<<dim3(3 * DMODEL / 128, M / 128), 256>>>(
        x, qkv_w, qkv_b, qkv_buf, M, 3 * DMODEL, DMODEL);

    // 2) RoPE on q,k in-place
    rope_kernel<<<(BATCH * T_SEQ * NHEAD) / 256, 256>>>();

    // 3) Causal flash attention -> g_attn [B*T, D]
    flash_kernel<<<dim3(T_SEQ / 128, NHEAD, BATCH), 128>>>();

    // 4) Output GEMM + bias: [4096,1024] x [1024,1024]
    sgemm_bias<<<dim3(DMODEL / 128, M / 128), 256>>>(
        attn_buf, out_w, out_b, out, M, DMODEL, DMODEL);
}

// round 2
// speedup vs baseline: 2.7044x; 2.7044x over previous
#include <cuda_runtime.h>
#include <math.h>
#include <stdint.h>

#define T_SEQ 2048
#define BATCH 2
#define NHEAD 16
#define HDIM 64
#define DMODEL 1024

// Scratch (allocation-free rule: __device__ globals)
__device__ float g_qkv[BATCH * T_SEQ * 3 * DMODEL];   // [B*T, 3*D]
__device__ float g_attn[BATCH * T_SEQ * DMODEL];      // [B*T, D]

// ---------------------------------------------------------------------------
// Helpers: tf32 convert + m16n8k8 tf32 MMA
// ---------------------------------------------------------------------------
__device__ __forceinline__ uint32_t f2tf(float x) {
    uint32_t r;
    asm("cvt.rna.tf32.f32 %0, %1;" : "=r"(r) : "f"(x));
    return r;
}

__device__ __forceinline__ void mma_tf32(float* d, const uint32_t* a, const uint32_t* b) {
    asm volatile(
        "mma.sync.aligned.m16n8k8.row.col.f32.tf32.tf32.f32 "
        "{%0,%1,%2,%3}, {%4,%5,%6,%7}, {%8,%9}, {%0,%1,%2,%3};"
        : "+f"(d[0]), "+f"(d[1]), "+f"(d[2]), "+f"(d[3])
        : "r"(a[0]), "r"(a[1]), "r"(a[2]), "r"(a[3]), "r"(b[0]), "r"(b[1]));
}

// ---------------------------------------------------------------------------
// TF32 tensor-core GEMM with bias: C[M,N] = A[M,K]*B[K,N] + bias
// 128x128x32 block tile, 256 threads (8 warps, 4x2), warp tile 32x64.
// Shared memory holds fragments in "fragment-major" order so fragment
// fetches are conflict-free vectorized LDS.
// ---------------------------------------------------------------------------
__global__ __launch_bounds__(256) void gemm_tf32(
    const float* __restrict__ A, const float* __restrict__ B,
    const float* __restrict__ bias, float* __restrict__ C,
    int M, int N, int K)
{
    __shared__ uint32_t As[4096];   // [mt 8][ks 4][lane 32][4]
    __shared__ uint32_t Bs[4096];   // [ks 4][nt 16][lane 32][2]

    int tid = threadIdx.x;
    int lane = tid & 31, warp = tid >> 5;
    int g = lane >> 2, tig = lane & 3;
    int bm = blockIdx.y * 128, bn = blockIdx.x * 128;
    int wm = warp & 3, wn = warp >> 2;

    float acc[2][8][4];
#pragma unroll
    for (int i = 0; i < 2; i++)
#pragma unroll
        for (int j = 0; j < 8; j++)
#pragma unroll
            for (int e = 0; e < 4; e++) acc[i][j][e] = 0.f;

    int arow = tid >> 3;          // 0..31
    int acol = (tid & 7) * 4;     // 0..28
    int bkr  = tid >> 3;          // 0..31
    int bnc  = (tid & 7) * 4;     // 0..28

    for (int k0 = 0; k0 < K; k0 += 32) {
        // ---- A tile (128x32) -> fragment-major shared
#pragma unroll
        for (int rb = 0; rb < 4; rb++) {
            int r = rb * 32 + arow;
            float4 v = *(const float4*)(A + (size_t)(bm + r) * K + k0 + acol);
            float vv[4] = {v.x, v.y, v.z, v.w};
            int mt = r >> 4, rr = r & 15, ir = rr >> 3, gg = rr & 7;
#pragma unroll
            for (int j = 0; j < 4; j++) {
                int c = acol + j;
                int ks = c >> 3, cc = c & 7, ic = cc >> 2, tg = cc & 3;
                As[(((mt * 4 + ks) * 32) + gg * 4 + tg) * 4 + ir + 2 * ic] = f2tf(vv[j]);
            }
        }
        // ---- B tile (32x128) -> fragment-major shared
        {
            int k = bkr;
            int ks = k >> 3, kk = k & 7, tg = kk & 3, ib = kk >> 2;
#pragma unroll
            for (int nb = 0; nb < 4; nb++) {
                int c0 = nb * 32 + bnc;
                float4 v = *(const float4*)(B + (size_t)(k0 + k) * N + bn + c0);
                float vv[4] = {v.x, v.y, v.z, v.w};
#pragma unroll
                for (int j = 0; j < 4; j++) {
                    int n = c0 + j;
                    int nt = n >> 3, gg = n & 7;
                    Bs[((ks * 16 + nt) * 32 + gg * 4 + tg) * 2 + ib] = f2tf(vv[j]);
                }
            }
        }
        __syncthreads();

#pragma unroll
        for (int ks = 0; ks < 4; ks++) {
            uint32_t af[2][4];
#pragma unroll
            for (int mt = 0; mt < 2; mt++) {
                uint4 t4 = *(const uint4*)&As[(((wm * 2 + mt) * 4 + ks) * 32 + lane) * 4];
                af[mt][0] = t4.x; af[mt][1] = t4.y; af[mt][2] = t4.z; af[mt][3] = t4.w;
            }
            uint32_t bf[8][2];
#pragma unroll
            for (int nt = 0; nt < 8; nt++) {
                uint2 t2 = *(const uint2*)&Bs[((ks * 16 + wn * 8 + nt) * 32 + lane) * 2];
                bf[nt][0] = t2.x; bf[nt][1] = t2.y;
            }
#pragma unroll
            for (int mt = 0; mt < 2; mt++)
#pragma unroll
                for (int nt = 0; nt < 8; nt++)
                    mma_tf32(acc[mt][nt], af[mt], bf[nt]);
        }
        __syncthreads();
    }

    // ---- epilogue: bias + store
#pragma unroll
    for (int mt = 0; mt < 2; mt++) {
        int row = bm + wm * 32 + mt * 16 + g;
#pragma unroll
        for (int nt = 0; nt < 8; nt++) {
            int col = bn + wn * 64 + nt * 8 + tig * 2;
            float bx = bias[col], by = bias[col + 1];
            float2 o0 = make_float2(acc[mt][nt][0] + bx, acc[mt][nt][1] + by);
            float2 o1 = make_float2(acc[mt][nt][2] + bx, acc[mt][nt][3] + by);
            *(float2*)(C + (size_t)row * N + col) = o0;
            *(float2*)(C + (size_t)(row + 8) * N + col) = o1;
        }
    }
}

// ---------------------------------------------------------------------------
// RoPE matching the reference's scrambled indexing (unchanged from R1).
// ---------------------------------------------------------------------------
__device__ __forceinline__ float invfreq(int i) {
    return exp2f(-(float)i * (13.287712379549449f / 32.0f));
}
__device__ __forceinline__ float rope_val(float tf, int i) {
    if (i < 32) return sinf(tf * invfreq(i));
    return cosf(tf * invfreq(i - 32));
}

__global__ void rope_kernel()
{
    int idx = blockIdx.x * blockDim.x + threadIdx.x;
    int h = idx % NHEAD;
    int t = (idx / NHEAD) % T_SEQ;
    int b = idx / (NHEAD * T_SEQ);
    float tf = (float)t;

    float sv[32], cv[32];
#pragma unroll
    for (int j = 0; j < 32; j++) {
        sv[j] = rope_val(tf, 2 * j);
        cv[j] = rope_val(tf, 2 * j + 1);
    }

    float* base = g_qkv + ((size_t)(b * T_SEQ + t)) * (3 * DMODEL) + h * HDIM;
#pragma unroll
    for (int s = 0; s < 2; s++) {
        float* p = base + s * DMODEL;
        float x[64];
#pragma unroll
        for (int d = 0; d < 64; d += 4) {
            float4 v = *(const float4*)(p + d);
            x[d] = v.x; x[d + 1] = v.y; x[d + 2] = v.z; x[d + 3] = v.w;
        }
        float o[64];
#pragma unroll
        for (int j = 0; j < 32; j++) {
            o[j]      = x[2 * j] * cv[j] - x[2 * j + 1] * sv[j];
            o[32 + j] = x[2 * j] * sv[j] + x[2 * j + 1] * cv[j];
        }
#pragma unroll
        for (int d = 0; d < 64; d += 4) {
            float4 v; v.x = o[d]; v.y = o[d + 1]; v.z = o[d + 2]; v.w = o[d + 3];
            *(float4*)(p + d) = v;
        }
    }
}

// ---------------------------------------------------------------------------
// Flash attention on tensor cores (tf32 mma). Block = 128 threads = 4 warps,
// 64 queries/block (16 per warp), 32-key tiles. K/V tiles in shared with
// pad-68 rows (conflict-free B-frag loads); P round-trips through per-warp
// shared (pad-36 rows, conflict-free A-frag loads). Online softmax in the
// mma C-fragment layout with shfl_xor row reductions.
// ---------------------------------------------------------------------------
__global__ __launch_bounds__(128) void flash_tf32()
{
    int qt = (gridDim.x - 1) - blockIdx.x;   // longest blocks launch first
    int h = blockIdx.y, b = blockIdx.z;
    int tid = threadIdx.x, warp = tid >> 5, lane = tid & 31;
    int g = lane >> 2, tig = lane & 3;
    int q0 = qt * 64 + warp * 16;

    __shared__ uint32_t Ksm[32 * 68];
    __shared__ uint32_t Vsm[32 * 68];
    __shared__ uint32_t Psm[4][16 * 36];

    // ---- Q fragments (held in registers, pre-scaled)
    const float scale = 0.125f;
    uint32_t qf[8][4];
    {
        const float* qb = g_qkv + ((size_t)(b * T_SEQ + q0)) * 3072 + h * 64;
#pragma unroll
        for (int ks = 0; ks < 8; ks++) {
            int c = ks * 8 + tig;
            qf[ks][0] = f2tf(qb[(size_t)g * 3072 + c] * scale);
            qf[ks][1] = f2tf(qb[(size_t)(g + 8) * 3072 + c] * scale);
            qf[ks][2] = f2tf(qb[(size_t)g * 3072 + c + 4] * scale);
            qf[ks][3] = f2tf(qb[(size_t)(g + 8) * 3072 + c + 4] * scale);
        }
    }

    float oacc[8][4];
#pragma unroll
    for (int i = 0; i < 8; i++)
#pragma unroll
        for (int e = 0; e < 4; e++) oacc[i][e] = 0.f;
    float m0 = -INFINITY, m1 = -INFINITY, l0 = 0.f, l1 = 0.f;

    int krow = tid >> 2;        // 0..31
    int kc = (tid & 3) * 16;    // 0,16,32,48

    int ntiles = 2 * qt + 2;
    for (int kt = 0; kt < ntiles; kt++) {
        int k0 = kt * 32;
        __syncthreads();
        // load K,V tile (32 keys x 64 dims each), cvt to tf32
        {
            const float* kr = g_qkv + ((size_t)(b * T_SEQ + k0 + krow)) * 3072
                              + 1024 + h * 64 + kc;
#pragma unroll
            for (int jj = 0; jj < 16; jj += 4) {
                float4 kv = *(const float4*)(kr + jj);
                float4 vv = *(const float4*)(kr + 1024 + jj);
                uint32_t* kd = &Ksm[krow * 68 + kc + jj];
                kd[0] = f2tf(kv.x); kd[1] = f2tf(kv.y);
                kd[2] = f2tf(kv.z); kd[3] = f2tf(kv.w);
                uint32_t* vd = &Vsm[krow * 68 + kc + jj];
                vd[0] = f2tf(vv.x); vd[1] = f2tf(vv.y);
                vd[2] = f2tf(vv.z); vd[3] = f2tf(vv.w);
            }
        }
        __syncthreads();

        // ---- S = Q K^T  (16q x 32k per warp)
        float sacc[4][4];
#pragma unroll
        for (int nt = 0; nt < 4; nt++)
#pragma unroll
            for (int e = 0; e < 4; e++) sacc[nt][e] = 0.f;
#pragma unroll
        for (int ks = 0; ks < 8; ks++) {
#pragma unroll
            for (int nt = 0; nt < 4; nt++) {
                uint32_t bf[2];
                bf[0] = Ksm[(nt * 8 + g) * 68 + ks * 8 + tig];
                bf[1] = Ksm[(nt * 8 + g) * 68 + ks * 8 + tig + 4];
                mma_tf32(sacc[nt], qf[ks], bf);
            }
        }

        // ---- causal mask (only near the diagonal)
        if (kt >= 2 * qt) {
#pragma unroll
            for (int nt = 0; nt < 4; nt++) {
                int key = k0 + nt * 8 + 2 * tig;
                if (key     > q0 + g)     sacc[nt][0] = -INFINITY;
                if (key + 1 > q0 + g)     sacc[nt][1] = -INFINITY;
                if (key     > q0 + 8 + g) sacc[nt][2] = -INFINITY;
                if (key + 1 > q0 + 8 + g) sacc[nt][3] = -INFINITY;
            }
        }

        // ---- online softmax
        float mx0 = -INFINITY, mx1 = -INFINITY;
#pragma unroll
        for (int nt = 0; nt < 4; nt++) {
            mx0 = fmaxf(mx0, fmaxf(sacc[nt][0], sacc[nt][1]));
            mx1 = fmaxf(mx1, fmaxf(sacc[nt][2], sacc[nt][3]));
        }
        mx0 = fmaxf(mx0, __shfl_xor_sync(0xffffffffu, mx0, 1));
        mx0 = fmaxf(mx0, __shfl_xor_sync(0xffffffffu, mx0, 2));
        mx1 = fmaxf(mx1, __shfl_xor_sync(0xffffffffu, mx1, 1));
        mx1 = fmaxf(mx1, __shfl_xor_sync(0xffffffffu, mx1, 2));

        float mn0 = fmaxf(m0, mx0), mn1 = fmaxf(m1, mx1);
        float a0 = __expf(m0 - mn0), a1 = __expf(m1 - mn1);
        m0 = mn0; m1 = mn1;
        l0 *= a0; l1 *= a1;
#pragma unroll
        for (int nd = 0; nd < 8; nd++) {
            oacc[nd][0] *= a0; oacc[nd][1] *= a0;
            oacc[nd][2] *= a1; oacc[nd][3] *= a1;
        }

        // ---- P = exp(S - m), write to per-warp shared (tf32)
        uint32_t* pw = Psm[warp];
#pragma unroll
        for (int nt = 0; nt < 4; nt++) {
            float p0 = __expf(sacc[nt][0] - mn0);
            float p1 = __expf(sacc[nt][1] - mn0);
            float p2 = __expf(sacc[nt][2] - mn1);
            float p3 = __expf(sacc[nt][3] - mn1);
            l0 += p0 + p1; l1 += p2 + p3;
            int col = nt * 8 + 2 * tig;
            uint2 lo = make_uint2(f2tf(p0), f2tf(p1));
            uint2 hi = make_uint2(f2tf(p2), f2tf(p3));
            *(uint2*)&pw[g * 36 + col] = lo;
            *(uint2*)&pw[(g + 8) * 36 + col] = hi;
        }
        __syncwarp();

        // ---- O += P V
#pragma unroll
        for (int kk = 0; kk < 4; kk++) {
            uint32_t af[4];
            af[0] = pw[g * 36 + kk * 8 + tig];
            af[1] = pw[(g + 8) * 36 + kk * 8 + tig];
            af[2] = pw[g * 36 + kk * 8 + tig + 4];
            af[3] = pw[(g + 8) * 36 + kk * 8 + tig + 4];
#pragma unroll
            for (int nd = 0; nd < 8; nd++) {
                uint32_t bf[2];
                bf[0] = Vsm[(kk * 8 + tig) * 68 + nd * 8 + g];
                bf[1] = Vsm[(kk * 8 + tig + 4) * 68 + nd * 8 + g];
                mma_tf32(oacc[nd], af, bf);
            }
        }
        __syncwarp();
    }

    // ---- finalize
    l0 += __shfl_xor_sync(0xffffffffu, l0, 1);
    l0 += __shfl_xor_sync(0xffffffffu, l0, 2);
    l1 += __shfl_xor_sync(0xffffffffu, l1, 1);
    l1 += __shfl_xor_sync(0xffffffffu, l1, 2);
    float i0 = 1.f / l0, i1 = 1.f / l1;

    float* ob = g_attn + ((size_t)(b * T_SEQ + q0)) * 1024 + h * 64;
#pragma unroll
    for (int nd = 0; nd < 8; nd++) {
        int col = nd * 8 + 2 * tig;
        float2 o0 = make_float2(oacc[nd][0] * i0, oacc[nd][1] * i0);
        float2 o1 = make_float2(oacc[nd][2] * i1, oacc[nd][3] * i1);
        *(float2*)&ob[(size_t)g * 1024 + col] = o0;
        *(float2*)&ob[(size_t)(g + 8) * 1024 + col] = o1;
    }
}

// ---------------------------------------------------------------------------
extern "C" void kernel_launch(void* const* d_in, const int* in_sizes, int n_in,
                              void* d_out, int out_size)
{
    const float* x      = (const float*)d_in[0];
    const float* qkv_w  = (const float*)d_in[1];
    const float* qkv_b  = (const float*)d_in[2];
    const float* out_w  = (const float*)d_in[3];
    const float* out_b  = (const float*)d_in[4];
    float* out = (float*)d_out;

    float *qkv_buf, *attn_buf;
    cudaGetSymbolAddress((void**)&qkv_buf, g_qkv);
    cudaGetSymbolAddress((void**)&attn_buf, g_attn);

    const int M = BATCH * T_SEQ;   // 4096

    // 1) QKV GEMM + bias: [4096,1024] x [1024,3072]
    gemm_tf32<<<dim3(3 * DMODEL / 128, M / 128), 256>>>(
        x, qkv_w, qkv_b, qkv_buf, M, 3 * DMODEL, DMODEL);

    // 2) RoPE on q,k in-place
    rope_kernel<<<(BATCH * T_SEQ * NHEAD) / 256, 256>>>();

    // 3) Causal flash attention (tf32 tensor cores) -> g_attn [B*T, D]
    flash_tf32<<<dim3(T_SEQ / 64, NHEAD, BATCH), 128>>>();

    // 4) Output GEMM + bias: [4096,1024] x [1024,1024]
    gemm_tf32<<<dim3(DMODEL / 128, M / 128), 256>>>(
        attn_buf, out_w, out_b, out, M, DMODEL, DMODEL);
}

// round 3
// speedup vs baseline: 3.9246x; 1.4512x over previous
#include <cuda_runtime.h>
#include <math.h>
#include <stdint.h>

#define T_SEQ 2048
#define BATCH 2
#define NHEAD 16
#define HDIM 64
#define DMODEL 1024

__device__ float g_qkv[BATCH * T_SEQ * 3 * DMODEL];   // [B*T, 3*D]
__device__ float g_attn[BATCH * T_SEQ * DMODEL];      // [B*T, D]

// ---------------------------------------------------------------------------
__device__ __forceinline__ uint32_t f2tf(float x) {
    uint32_t r;
    asm("cvt.rna.tf32.f32 %0, %1;" : "=r"(r) : "f"(x));
    return r;
}

__device__ __forceinline__ void mma_tf32(float* d, const uint32_t* a, const uint32_t* b) {
    asm volatile(
        "mma.sync.aligned.m16n8k8.row.col.f32.tf32.tf32.f32 "
        "{%0,%1,%2,%3}, {%4,%5,%6,%7}, {%8,%9}, {%0,%1,%2,%3};"
        : "+f"(d[0]), "+f"(d[1]), "+f"(d[2]), "+f"(d[3])
        : "r"(a[0]), "r"(a[1]), "r"(a[2]), "r"(a[3]), "r"(b[0]), "r"(b[1]));
}

__device__ __forceinline__ void cpa16(uint32_t saddr, const void* g) {
    asm volatile("cp.async.cg.shared.global [%0], [%1], 16;" :: "r"(saddr), "l"(g));
}
__device__ __forceinline__ void cpa_commit() {
    asm volatile("cp.async.commit_group;");
}
__device__ __forceinline__ void cpa_wait1() {
    asm volatile("cp.async.wait_group 1;");
}

// ---------------------------------------------------------------------------
// TF32 tensor GEMM, 128x128x32 tiles, cp.async double-buffered.
// Shared: A row-major [128][36] (pad), B row-major [32][136] (pad).
// Fragment LDS provably bank-conflict-free; cvt to tf32 at fragment load.
// ---------------------------------------------------------------------------
#define ASZ (128 * 36)
#define BSZ (32 * 136)
#define BUFSZ (ASZ + BSZ)

__global__ __launch_bounds__(256) void gemm_tf32(
    const float* __restrict__ A, const float* __restrict__ B,
    const float* __restrict__ bias, float* __restrict__ C,
    int M, int N, int K)
{
    extern __shared__ float smem[];

    int tid = threadIdx.x;
    int lane = tid & 31, warp = tid >> 5;
    int g = lane >> 2, tig = lane & 3;
    int bm = blockIdx.y * 128, bn = blockIdx.x * 128;
    int wm = warp & 3, wn = warp >> 2;

    float acc[2][8][4];
#pragma unroll
    for (int i = 0; i < 2; i++)
#pragma unroll
        for (int j = 0; j < 8; j++)
#pragma unroll
            for (int e = 0; e < 4; e++) acc[i][j][e] = 0.f;

    uint32_t smem_base = (uint32_t)__cvta_generic_to_shared(smem);

    // issue cp.async for one K-tile into buffer `buf`
    auto issue = [&](int k0, int buf) {
        uint32_t abase = smem_base + buf * BUFSZ * 4;
        uint32_t bbase = abase + ASZ * 4;
#pragma unroll
        for (int i = 0; i < 4; i++) {
            int c = tid + i * 256;              // 0..1023 A chunks
            int row = c >> 3, col4 = (c & 7) * 4;
            cpa16(abase + (row * 36 + col4) * 4,
                  A + (size_t)(bm + row) * K + k0 + col4);
        }
#pragma unroll
        for (int i = 0; i < 4; i++) {
            int c = tid + i * 256;              // 0..1023 B chunks
            int row = c >> 5, col4 = (c & 31) * 4;
            cpa16(bbase + (row * 136 + col4) * 4,
                  B + (size_t)(k0 + row) * N + bn + col4);
        }
        cpa_commit();
    };

    int ntiles = K / 32;
    issue(0, 0);

    for (int kt = 0; kt < ntiles; kt++) {
        if (kt + 1 < ntiles) issue((kt + 1) * 32, (kt + 1) & 1);
        else cpa_commit();                       // empty group keeps wait math uniform
        cpa_wait1();
        __syncthreads();

        const float* As = smem + (kt & 1) * BUFSZ;
        const float* Bs = As + ASZ;

#pragma unroll
        for (int ks = 0; ks < 4; ks++) {
            uint32_t af[2][4];
#pragma unroll
            for (int mt = 0; mt < 2; mt++) {
                int r0 = wm * 32 + mt * 16;
                int c0 = ks * 8;
                af[mt][0] = f2tf(As[(r0 + g) * 36 + c0 + tig]);
                af[mt][1] = f2tf(As[(r0 + 8 + g) * 36 + c0 + tig]);
                af[mt][2] = f2tf(As[(r0 + g) * 36 + c0 + tig + 4]);
                af[mt][3] = f2tf(As[(r0 + 8 + g) * 36 + c0 + tig + 4]);
            }
            uint32_t bf[8][2];
#pragma unroll
            for (int nt = 0; nt < 8; nt++) {
                int n = wn * 64 + nt * 8 + g;
                bf[nt][0] = f2tf(Bs[(ks * 8 + tig) * 136 + n]);
                bf[nt][1] = f2tf(Bs[(ks * 8 + tig + 4) * 136 + n]);
            }
#pragma unroll
            for (int mt = 0; mt < 2; mt++)
#pragma unroll
                for (int nt = 0; nt < 8; nt++)
                    mma_tf32(acc[mt][nt], af[mt], bf[nt]);
        }
        __syncthreads();
    }

#pragma unroll
    for (int mt = 0; mt < 2; mt++) {
        int row = bm + wm * 32 + mt * 16 + g;
#pragma unroll
        for (int nt = 0; nt < 8; nt++) {
            int col = bn + wn * 64 + nt * 8 + tig * 2;
            float bx = bias[col], by = bias[col + 1];
            float2 o0 = make_float2(acc[mt][nt][0] + bx, acc[mt][nt][1] + by);
            float2 o1 = make_float2(acc[mt][nt][2] + bx, acc[mt][nt][3] + by);
            *(float2*)(C + (size_t)row * N + col) = o0;
            *(float2*)(C + (size_t)(row + 8) * N + col) = o1;
        }
    }
}

// ---------------------------------------------------------------------------
// RoPE with the reference's scrambled indexing (unchanged).
// ---------------------------------------------------------------------------
__device__ __forceinline__ float invfreq(int i) {
    return exp2f(-(float)i * (13.287712379549449f / 32.0f));
}
__device__ __forceinline__ float rope_val(float tf, int i) {
    if (i < 32) return sinf(tf * invfreq(i));
    return cosf(tf * invfreq(i - 32));
}

__global__ void rope_kernel()
{
    int idx = blockIdx.x * blockDim.x + threadIdx.x;
    int h = idx % NHEAD;
    int t = (idx / NHEAD) % T_SEQ;
    int b = idx / (NHEAD * T_SEQ);
    float tf = (float)t;

    float sv[32], cv[32];
#pragma unroll
    for (int j = 0; j < 32; j++) {
        sv[j] = rope_val(tf, 2 * j);
        cv[j] = rope_val(tf, 2 * j + 1);
    }

    float* base = g_qkv + ((size_t)(b * T_SEQ + t)) * (3 * DMODEL) + h * HDIM;
#pragma unroll
    for (int s = 0; s < 2; s++) {
        float* p = base + s * DMODEL;
        float x[64];
#pragma unroll
        for (int d = 0; d < 64; d += 4) {
            float4 v = *(const float4*)(p + d);
            x[d] = v.x; x[d + 1] = v.y; x[d + 2] = v.z; x[d + 3] = v.w;
        }
        float o[64];
#pragma unroll
        for (int j = 0; j < 32; j++) {
            o[j]      = x[2 * j] * cv[j] - x[2 * j + 1] * sv[j];
            o[32 + j] = x[2 * j] * sv[j] + x[2 * j + 1] * cv[j];
        }
#pragma unroll
        for (int d = 0; d < 64; d += 4) {
            float4 v; v.x = o[d]; v.y = o[d + 1]; v.z = o[d + 2]; v.w = o[d + 3];
            *(float4*)(p + d) = v;
        }
    }
}

// ---------------------------------------------------------------------------
// Flash attention, tf32 mma, cp.async double-buffered K/V tiles.
// K/V shared rows padded to 72 floats (conflict-free fragment LDS).
// ---------------------------------------------------------------------------
__global__ __launch_bounds__(128) void flash_tf32()
{
    int qt = (gridDim.x - 1) - blockIdx.x;
    int h = blockIdx.y, b = blockIdx.z;
    int tid = threadIdx.x, warp = tid >> 5, lane = tid & 31;
    int g = lane >> 2, tig = lane & 3;
    int q0 = qt * 64 + warp * 16;

    __shared__ float Ks[2][32 * 72];
    __shared__ float Vs[2][32 * 72];
    __shared__ uint32_t Psm[4][16 * 36];

    uint32_t kbase = (uint32_t)__cvta_generic_to_shared(&Ks[0][0]);
    uint32_t vbase = (uint32_t)__cvta_generic_to_shared(&Vs[0][0]);

    auto issue = [&](int k0, int buf) {
        uint32_t kb = kbase + buf * (32 * 72 * 4);
        uint32_t vb = vbase + buf * (32 * 72 * 4);
#pragma unroll
        for (int i = 0; i < 4; i++) {
            int c = tid + i * 128;              // 0..511 chunks (16B)
            int row = c >> 4, col4 = (c & 15) * 4;
            const float* kg = g_qkv + ((size_t)(b * T_SEQ + k0 + row)) * 3072
                              + 1024 + h * 64 + col4;
            cpa16(kb + (row * 72 + col4) * 4, kg);
            cpa16(vb + (row * 72 + col4) * 4, kg + 1024);
        }
        cpa_commit();
    };

    // Q fragments (pre-scaled, tf32)
    const float scale = 0.125f;
    uint32_t qf[8][4];
    {
        const float* qb = g_qkv + ((size_t)(b * T_SEQ + q0)) * 3072 + h * 64;
#pragma unroll
        for (int ks = 0; ks < 8; ks++) {
            int c = ks * 8 + tig;
            qf[ks][0] = f2tf(qb[(size_t)g * 3072 + c] * scale);
            qf[ks][1] = f2tf(qb[(size_t)(g + 8) * 3072 + c] * scale);
            qf[ks][2] = f2tf(qb[(size_t)g * 3072 + c + 4] * scale);
            qf[ks][3] = f2tf(qb[(size_t)(g + 8) * 3072 + c + 4] * scale);
        }
    }

    float oacc[8][4];
#pragma unroll
    for (int i = 0; i < 8; i++)
#pragma unroll
        for (int e = 0; e < 4; e++) oacc[i][e] = 0.f;
    float m0 = -INFINITY, m1 = -INFINITY, l0 = 0.f, l1 = 0.f;

    int ntiles = 2 * qt + 2;
    issue(0, 0);

    for (int kt = 0; kt < ntiles; kt++) {
        int k0 = kt * 32;
        if (kt + 1 < ntiles) issue((kt + 1) * 32, (kt + 1) & 1);
        else cpa_commit();
        cpa_wait1();
        __syncthreads();

        const float* Kb = Ks[kt & 1];
        const float* Vb = Vs[kt & 1];

        // ---- S = Q K^T
        float sacc[4][4];
#pragma unroll
        for (int nt = 0; nt < 4; nt++)
#pragma unroll
            for (int e = 0; e < 4; e++) sacc[nt][e] = 0.f;
#pragma unroll
        for (int ks = 0; ks < 8; ks++) {
#pragma unroll
            for (int nt = 0; nt < 4; nt++) {
                uint32_t bf[2];
                bf[0] = f2tf(Kb[(nt * 8 + g) * 72 + ks * 8 + tig]);
                bf[1] = f2tf(Kb[(nt * 8 + g) * 72 + ks * 8 + tig + 4]);
                mma_tf32(sacc[nt], qf[ks], bf);
            }
        }

        // ---- causal mask near diagonal
        if (kt >= 2 * qt) {
#pragma unroll
            for (int nt = 0; nt < 4; nt++) {
                int key = k0 + nt * 8 + 2 * tig;
                if (key     > q0 + g)     sacc[nt][0] = -INFINITY;
                if (key + 1 > q0 + g)     sacc[nt][1] = -INFINITY;
                if (key     > q0 + 8 + g) sacc[nt][2] = -INFINITY;
                if (key + 1 > q0 + 8 + g) sacc[nt][3] = -INFINITY;
            }
        }

        // ---- online softmax
        float mx0 = -INFINITY, mx1 = -INFINITY;
#pragma unroll
        for (int nt = 0; nt < 4; nt++) {
            mx0 = fmaxf(mx0, fmaxf(sacc[nt][0], sacc[nt][1]));
            mx1 = fmaxf(mx1, fmaxf(sacc[nt][2], sacc[nt][3]));
        }
        mx0 = fmaxf(mx0, __shfl_xor_sync(0xffffffffu, mx0, 1));
        mx0 = fmaxf(mx0, __shfl_xor_sync(0xffffffffu, mx0, 2));
        mx1 = fmaxf(mx1, __shfl_xor_sync(0xffffffffu, mx1, 1));
        mx1 = fmaxf(mx1, __shfl_xor_sync(0xffffffffu, mx1, 2));

        float mn0 = fmaxf(m0, mx0), mn1 = fmaxf(m1, mx1);
        float a0 = __expf(m0 - mn0), a1 = __expf(m1 - mn1);
        m0 = mn0; m1 = mn1;
        l0 *= a0; l1 *= a1;
#pragma unroll
        for (int nd = 0; nd < 8; nd++) {
            oacc[nd][0] *= a0; oacc[nd][1] *= a0;
            oacc[nd][2] *= a1; oacc[nd][3] *= a1;
        }

        // ---- P = exp(S - m) to per-warp shared (tf32)
        uint32_t* pw = Psm[warp];
#pragma unroll
        for (int nt = 0; nt < 4; nt++) {
            float p0 = __expf(sacc[nt][0] - mn0);
            float p1 = __expf(sacc[nt][1] - mn0);
            float p2 = __expf(sacc[nt][2] - mn1);
            float p3 = __expf(sacc[nt][3] - mn1);
            l0 += p0 + p1; l1 += p2 + p3;
            int col = nt * 8 + 2 * tig;
            uint2 lo = make_uint2(f2tf(p0), f2tf(p1));
            uint2 hi = make_uint2(f2tf(p2), f2tf(p3));
            *(uint2*)&pw[g * 36 + col] = lo;
            *(uint2*)&pw[(g + 8) * 36 + col] = hi;
        }
        __syncwarp();

        // ---- O += P V
#pragma unroll
        for (int kk = 0; kk < 4; kk++) {
            uint32_t af[4];
            af[0] = pw[g * 36 + kk * 8 + tig];
            af[1] = pw[(g + 8) * 36 + kk * 8 + tig];
            af[2] = pw[g * 36 + kk * 8 + tig + 4];
            af[3] = pw[(g + 8) * 36 + kk * 8 + tig + 4];
#pragma unroll
            for (int nd = 0; nd < 8; nd++) {
                uint32_t bf[2];
                bf[0] = f2tf(Vb[(kk * 8 + tig) * 72 + nd * 8 + g]);
                bf[1] = f2tf(Vb[(kk * 8 + tig + 4) * 72 + nd * 8 + g]);
                mma_tf32(oacc[nd], af, bf);
            }
        }
        __syncwarp();
        __syncthreads();
    }

    // ---- finalize
    l0 += __shfl_xor_sync(0xffffffffu, l0, 1);
    l0 += __shfl_xor_sync(0xffffffffu, l0, 2);
    l1 += __shfl_xor_sync(0xffffffffu, l1, 1);
    l1 += __shfl_xor_sync(0xffffffffu, l1, 2);
    float i0 = 1.f / l0, i1 = 1.f / l1;

    float* ob = g_attn + ((size_t)(b * T_SEQ + q0)) * 1024 + h * 64;
#pragma unroll
    for (int nd = 0; nd < 8; nd++) {
        int col = nd * 8 + 2 * tig;
        float2 o0 = make_float2(oacc[nd][0] * i0, oacc[nd][1] * i0);
        float2 o1 = make_float2(oacc[nd][2] * i1, oacc[nd][3] * i1);
        *(float2*)&ob[(size_t)g * 1024 + col] = o0;
        *(float2*)&ob[(size_t)(g + 8) * 1024 + col] = o1;
    }
}

// ---------------------------------------------------------------------------
extern "C" void kernel_launch(void* const* d_in, const int* in_sizes, int n_in,
                              void* d_out, int out_size)
{
    const float* x      = (const float*)d_in[0];
    const float* qkv_w  = (const float*)d_in[1];
    const float* qkv_b  = (const float*)d_in[2];
    const float* out_w  = (const float*)d_in[3];
    const float* out_b  = (const float*)d_in[4];
    float* out = (float*)d_out;

    float *qkv_buf, *attn_buf;
    cudaGetSymbolAddress((void**)&qkv_buf, g_qkv);
    cudaGetSymbolAddress((void**)&attn_buf, g_attn);

    const int M = BATCH * T_SEQ;   // 4096
    const int gemm_smem = 2 * BUFSZ * 4;   // 71680 B

    cudaFuncSetAttribute(gemm_tf32, cudaFuncAttributeMaxDynamicSharedMemorySize,
                         gemm_smem);

    gemm_tf32<<<dim3(3 * DMODEL / 128, M / 128), 256, gemm_smem>>>(
        x, qkv_w, qkv_b, qkv_buf, M, 3 * DMODEL, DMODEL);

    rope_kernel<<<(BATCH * T_SEQ * NHEAD) / 256, 256>>>();

    flash_tf32<<<dim3(T_SEQ / 64, NHEAD, BATCH), 128>>>();

    gemm_tf32<<<dim3(DMODEL / 128, M / 128), 256, gemm_smem>>>(
        attn_buf, out_w, out_b, out, M, DMODEL, DMODEL);
}

// round 4
// speedup vs baseline: 4.1740x; 1.0636x over previous
#include <cuda_runtime.h>
#include <math.h>
#include <stdint.h>

#define T_SEQ 2048
#define BATCH 2
#define NHEAD 16
#define HDIM 64
#define DMODEL 1024

__device__ float g_qkv[BATCH * T_SEQ * 3 * DMODEL];   // [B*T, 3*D]
__device__ float g_attn[BATCH * T_SEQ * DMODEL];      // [B*T, D] (tf32-rounded)
__device__ float g_xtf[BATCH * T_SEQ * DMODEL];       // x, tf32-rounded
__device__ float g_wtf[DMODEL * 3 * DMODEL];          // qkv_w, tf32-rounded
__device__ float g_owtf[DMODEL * DMODEL];             // out_w, tf32-rounded

// ---------------------------------------------------------------------------
__device__ __forceinline__ uint32_t f2tf(float x) {
    uint32_t r;
    asm("cvt.rna.tf32.f32 %0, %1;" : "=r"(r) : "f"(x));
    return r;
}

__device__ __forceinline__ void mma_tf32(float* d, const uint32_t* a, const uint32_t* b) {
    asm volatile(
        "mma.sync.aligned.m16n8k8.row.col.f32.tf32.tf32.f32 "
        "{%0,%1,%2,%3}, {%4,%5,%6,%7}, {%8,%9}, {%0,%1,%2,%3};"
        : "+f"(d[0]), "+f"(d[1]), "+f"(d[2]), "+f"(d[3])
        : "r"(a[0]), "r"(a[1]), "r"(a[2]), "r"(a[3]), "r"(b[0]), "r"(b[1]));
}

__device__ __forceinline__ void cpa16(uint32_t saddr, const void* g) {
    asm volatile("cp.async.cg.shared.global [%0], [%1], 16;" :: "r"(saddr), "l"(g));
}
__device__ __forceinline__ void cpa_commit() {
    asm volatile("cp.async.commit_group;");
}
__device__ __forceinline__ void cpa_wait1() {
    asm volatile("cp.async.wait_group 1;");
}

// ---------------------------------------------------------------------------
// Pre-round a float array to tf32 (grid-stride over float4).
// ---------------------------------------------------------------------------
__global__ void round_tf32(const float* __restrict__ src, float* __restrict__ dst, int n4)
{
    int i = blockIdx.x * blockDim.x + threadIdx.x;
    if (i < n4) {
        float4 v = ((const float4*)src)[i];
        v.x = __uint_as_float(f2tf(v.x));
        v.y = __uint_as_float(f2tf(v.y));
        v.z = __uint_as_float(f2tf(v.z));
        v.w = __uint_as_float(f2tf(v.w));
        ((float4*)dst)[i] = v;
    }
}

// ---------------------------------------------------------------------------
// TF32 tensor GEMM, 128x128x32 tiles, cp.async double-buffered.
// Inputs are PRE-ROUNDED to tf32: fragment loads are plain bit-casts.
// ---------------------------------------------------------------------------
#define ASZ (128 * 36)
#define BSZ (32 * 136)
#define BUFSZ (ASZ + BSZ)

__global__ __launch_bounds__(256, 2) void gemm_tf32(
    const float* __restrict__ A, const float* __restrict__ B,
    const float* __restrict__ bias, float* __restrict__ C,
    int M, int N, int K)
{
    extern __shared__ float smem[];

    int tid = threadIdx.x;
    int lane = tid & 31, warp = tid >> 5;
    int g = lane >> 2, tig = lane & 3;
    int bm = blockIdx.y * 128, bn = blockIdx.x * 128;
    int wm = warp & 3, wn = warp >> 2;

    float acc[2][8][4];
#pragma unroll
    for (int i = 0; i < 2; i++)
#pragma unroll
        for (int j = 0; j < 8; j++)
#pragma unroll
            for (int e = 0; e < 4; e++) acc[i][j][e] = 0.f;

    uint32_t smem_base = (uint32_t)__cvta_generic_to_shared(smem);

    auto issue = [&](int k0, int buf) {
        uint32_t abase = smem_base + buf * BUFSZ * 4;
        uint32_t bbase = abase + ASZ * 4;
#pragma unroll
        for (int i = 0; i < 4; i++) {
            int c = tid + i * 256;
            int row = c >> 3, col4 = (c & 7) * 4;
            cpa16(abase + (row * 36 + col4) * 4,
                  A + (size_t)(bm + row) * K + k0 + col4);
        }
#pragma unroll
        for (int i = 0; i < 4; i++) {
            int c = tid + i * 256;
            int row = c >> 5, col4 = (c & 31) * 4;
            cpa16(bbase + (row * 136 + col4) * 4,
                  B + (size_t)(k0 + row) * N + bn + col4);
        }
        cpa_commit();
    };

    int ntiles = K / 32;
    issue(0, 0);

    for (int kt = 0; kt < ntiles; kt++) {
        if (kt + 1 < ntiles) issue((kt + 1) * 32, (kt + 1) & 1);
        else cpa_commit();
        cpa_wait1();
        __syncthreads();

        const float* As = smem + (kt & 1) * BUFSZ;
        const float* Bs = As + ASZ;
        const float* Ar0 = As + (wm * 32 + g) * 36;
        const float* Ar1 = Ar0 + 8 * 36;
        const float* Br0 = Bs + tig * 136 + wn * 64 + g;
        const float* Br1 = Br0 + 4 * 136;

#pragma unroll
        for (int ks = 0; ks < 4; ks++) {
            int c0 = ks * 8;
            uint32_t af[2][4];
#pragma unroll
            for (int mt = 0; mt < 2; mt++) {
                const float* a0 = Ar0 + mt * 16 * 36;
                const float* a1 = Ar1 + mt * 16 * 36;
                af[mt][0] = __float_as_uint(a0[c0 + tig]);
                af[mt][1] = __float_as_uint(a1[c0 + tig]);
                af[mt][2] = __float_as_uint(a0[c0 + tig + 4]);
                af[mt][3] = __float_as_uint(a1[c0 + tig + 4]);
            }
            uint32_t bf[8][2];
#pragma unroll
            for (int nt = 0; nt < 8; nt++) {
                bf[nt][0] = __float_as_uint(Br0[ks * 8 * 136 + nt * 8]);
                bf[nt][1] = __float_as_uint(Br1[ks * 8 * 136 + nt * 8]);
            }
#pragma unroll
            for (int mt = 0; mt < 2; mt++)
#pragma unroll
                for (int nt = 0; nt < 8; nt++)
                    mma_tf32(acc[mt][nt], af[mt], bf[nt]);
        }
        __syncthreads();
    }

#pragma unroll
    for (int mt = 0; mt < 2; mt++) {
        int row = bm + wm * 32 + mt * 16 + g;
#pragma unroll
        for (int nt = 0; nt < 8; nt++) {
            int col = bn + wn * 64 + nt * 8 + tig * 2;
            float bx = bias[col], by = bias[col + 1];
            float2 o0 = make_float2(acc[mt][nt][0] + bx, acc[mt][nt][1] + by);
            float2 o1 = make_float2(acc[mt][nt][2] + bx, acc[mt][nt][3] + by);
            *(float2*)(C + (size_t)row * N + col) = o0;
            *(float2*)(C + (size_t)(row + 8) * N + col) = o1;
        }
    }
}

// ---------------------------------------------------------------------------
// RoPE (reference's scrambled indexing). Writes q,k tf32-rounded; also
// rounds v in place so flash fragment loads are bit-casts.
// ---------------------------------------------------------------------------
__device__ __forceinline__ float invfreq(int i) {
    return exp2f(-(float)i * (13.287712379549449f / 32.0f));
}
__device__ __forceinline__ float rope_val(float tf, int i) {
    if (i < 32) return sinf(tf * invfreq(i));
    return cosf(tf * invfreq(i - 32));
}

__global__ void rope_kernel()
{
    int idx = blockIdx.x * blockDim.x + threadIdx.x;
    int h = idx % NHEAD;
    int t = (idx / NHEAD) % T_SEQ;
    int b = idx / (NHEAD * T_SEQ);
    float tf = (float)t;

    float sv[32], cv[32];
#pragma unroll
    for (int j = 0; j < 32; j++) {
        sv[j] = rope_val(tf, 2 * j);
        cv[j] = rope_val(tf, 2 * j + 1);
    }

    float* base = g_qkv + ((size_t)(b * T_SEQ + t)) * (3 * DMODEL) + h * HDIM;
#pragma unroll
    for (int s = 0; s < 2; s++) {
        float* p = base + s * DMODEL;
        float x[64];
#pragma unroll
        for (int d = 0; d < 64; d += 4) {
            float4 v = *(const float4*)(p + d);
            x[d] = v.x; x[d + 1] = v.y; x[d + 2] = v.z; x[d + 3] = v.w;
        }
        float o[64];
#pragma unroll
        for (int j = 0; j < 32; j++) {
            o[j]      = x[2 * j] * cv[j] - x[2 * j + 1] * sv[j];
            o[32 + j] = x[2 * j] * sv[j] + x[2 * j + 1] * cv[j];
        }
#pragma unroll
        for (int d = 0; d < 64; d += 4) {
            float4 v;
            v.x = __uint_as_float(f2tf(o[d]));
            v.y = __uint_as_float(f2tf(o[d + 1]));
            v.z = __uint_as_float(f2tf(o[d + 2]));
            v.w = __uint_as_float(f2tf(o[d + 3]));
            *(float4*)(p + d) = v;
        }
    }
    // round v in place
    float* pv = base + 2 * DMODEL;
#pragma unroll
    for (int d = 0; d < 64; d += 4) {
        float4 v = *(const float4*)(pv + d);
        v.x = __uint_as_float(f2tf(v.x));
        v.y = __uint_as_float(f2tf(v.y));
        v.z = __uint_as_float(f2tf(v.z));
        v.w = __uint_as_float(f2tf(v.w));
        *(float4*)(pv + d) = v;
    }
}

// ---------------------------------------------------------------------------
// Flash attention, tf32 mma, cp.async double-buffered K/V (pre-rounded).
// ---------------------------------------------------------------------------
__global__ __launch_bounds__(128) void flash_tf32()
{
    int qt = (gridDim.x - 1) - blockIdx.x;
    int h = blockIdx.y, b = blockIdx.z;
    int tid = threadIdx.x, warp = tid >> 5, lane = tid & 31;
    int g = lane >> 2, tig = lane & 3;
    int q0 = qt * 64 + warp * 16;

    __shared__ float Ks[2][32 * 72];
    __shared__ float Vs[2][32 * 72];
    __shared__ uint32_t Psm[4][16 * 36];

    uint32_t kbase = (uint32_t)__cvta_generic_to_shared(&Ks[0][0]);
    uint32_t vbase = (uint32_t)__cvta_generic_to_shared(&Vs[0][0]);

    auto issue = [&](int k0, int buf) {
        uint32_t kb = kbase + buf * (32 * 72 * 4);
        uint32_t vb = vbase + buf * (32 * 72 * 4);
#pragma unroll
        for (int i = 0; i < 4; i++) {
            int c = tid + i * 128;
            int row = c >> 4, col4 = (c & 15) * 4;
            const float* kg = g_qkv + ((size_t)(b * T_SEQ + k0 + row)) * 3072
                              + 1024 + h * 64 + col4;
            cpa16(kb + (row * 72 + col4) * 4, kg);
            cpa16(vb + (row * 72 + col4) * 4, kg + 1024);
        }
        cpa_commit();
    };

    const float scale = 0.125f;    // exact power of two: preserves tf32 rounding
    uint32_t qf[8][4];
    {
        const float* qb = g_qkv + ((size_t)(b * T_SEQ + q0)) * 3072 + h * 64;
#pragma unroll
        for (int ks = 0; ks < 8; ks++) {
            int c = ks * 8 + tig;
            qf[ks][0] = __float_as_uint(qb[(size_t)g * 3072 + c] * scale);
            qf[ks][1] = __float_as_uint(qb[(size_t)(g + 8) * 3072 + c] * scale);
            qf[ks][2] = __float_as_uint(qb[(size_t)g * 3072 + c + 4] * scale);
            qf[ks][3] = __float_as_uint(qb[(size_t)(g + 8) * 3072 + c + 4] * scale);
        }
    }

    float oacc[8][4];
#pragma unroll
    for (int i = 0; i < 8; i++)
#pragma unroll
        for (int e = 0; e < 4; e++) oacc[i][e] = 0.f;
    float m0 = -INFINITY, m1 = -INFINITY, l0 = 0.f, l1 = 0.f;

    int ntiles = 2 * qt + 2;
    issue(0, 0);

    for (int kt = 0; kt < ntiles; kt++) {
        int k0 = kt * 32;
        if (kt + 1 < ntiles) issue((kt + 1) * 32, (kt + 1) & 1);
        else cpa_commit();
        cpa_wait1();
        __syncthreads();

        const float* Kb = Ks[kt & 1];
        const float* Vb = Vs[kt & 1];

        float sacc[4][4];
#pragma unroll
        for (int nt = 0; nt < 4; nt++)
#pragma unroll
            for (int e = 0; e < 4; e++) sacc[nt][e] = 0.f;
#pragma unroll
        for (int ks = 0; ks < 8; ks++) {
#pragma unroll
            for (int nt = 0; nt < 4; nt++) {
                uint32_t bf[2];
                bf[0] = __float_as_uint(Kb[(nt * 8 + g) * 72 + ks * 8 + tig]);
                bf[1] = __float_as_uint(Kb[(nt * 8 + g) * 72 + ks * 8 + tig + 4]);
                mma_tf32(sacc[nt], qf[ks], bf);
            }
        }

        if (kt >= 2 * qt) {
#pragma unroll
            for (int nt = 0; nt < 4; nt++) {
                int key = k0 + nt * 8 + 2 * tig;
                if (key     > q0 + g)     sacc[nt][0] = -INFINITY;
                if (key + 1 > q0 + g)     sacc[nt][1] = -INFINITY;
                if (key     > q0 + 8 + g) sacc[nt][2] = -INFINITY;
                if (key + 1 > q0 + 8 + g) sacc[nt][3] = -INFINITY;
            }
        }

        float mx0 = -INFINITY, mx1 = -INFINITY;
#pragma unroll
        for (int nt = 0; nt < 4; nt++) {
            mx0 = fmaxf(mx0, fmaxf(sacc[nt][0], sacc[nt][1]));
            mx1 = fmaxf(mx1, fmaxf(sacc[nt][2], sacc[nt][3]));
        }
        mx0 = fmaxf(mx0, __shfl_xor_sync(0xffffffffu, mx0, 1));
        mx0 = fmaxf(mx0, __shfl_xor_sync(0xffffffffu, mx0, 2));
        mx1 = fmaxf(mx1, __shfl_xor_sync(0xffffffffu, mx1, 1));
        mx1 = fmaxf(mx1, __shfl_xor_sync(0xffffffffu, mx1, 2));

        float mn0 = fmaxf(m0, mx0), mn1 = fmaxf(m1, mx1);
        float a0 = __expf(m0 - mn0), a1 = __expf(m1 - mn1);
        m0 = mn0; m1 = mn1;
        l0 *= a0; l1 *= a1;
#pragma unroll
        for (int nd = 0; nd < 8; nd++) {
            oacc[nd][0] *= a0; oacc[nd][1] *= a0;
            oacc[nd][2] *= a1; oacc[nd][3] *= a1;
        }

        uint32_t* pw = Psm[warp];
#pragma unroll
        for (int nt = 0; nt < 4; nt++) {
            float p0 = __expf(sacc[nt][0] - mn0);
            float p1 = __expf(sacc[nt][1] - mn0);
            float p2 = __expf(sacc[nt][2] - mn1);
            float p3 = __expf(sacc[nt][3] - mn1);
            l0 += p0 + p1; l1 += p2 + p3;
            int col = nt * 8 + 2 * tig;
            uint2 lo = make_uint2(f2tf(p0), f2tf(p1));
            uint2 hi = make_uint2(f2tf(p2), f2tf(p3));
            *(uint2*)&pw[g * 36 + col] = lo;
            *(uint2*)&pw[(g + 8) * 36 + col] = hi;
        }
        __syncwarp();

#pragma unroll
        for (int kk = 0; kk < 4; kk++) {
            uint32_t af[4];
            af[0] = pw[g * 36 + kk * 8 + tig];
            af[1] = pw[(g + 8) * 36 + kk * 8 + tig];
            af[2] = pw[g * 36 + kk * 8 + tig + 4];
            af[3] = pw[(g + 8) * 36 + kk * 8 + tig + 4];
#pragma unroll
            for (int nd = 0; nd < 8; nd++) {
                uint32_t bf[2];
                bf[0] = __float_as_uint(Vb[(kk * 8 + tig) * 72 + nd * 8 + g]);
                bf[1] = __float_as_uint(Vb[(kk * 8 + tig + 4) * 72 + nd * 8 + g]);
                mma_tf32(oacc[nd], af, bf);
            }
        }
        __syncwarp();
        __syncthreads();
    }

    l0 += __shfl_xor_sync(0xffffffffu, l0, 1);
    l0 += __shfl_xor_sync(0xffffffffu, l0, 2);
    l1 += __shfl_xor_sync(0xffffffffu, l1, 1);
    l1 += __shfl_xor_sync(0xffffffffu, l1, 2);
    float i0 = 1.f / l0, i1 = 1.f / l1;

    // store tf32-rounded so the out-GEMM bit-casts
    float* ob = g_attn + ((size_t)(b * T_SEQ + q0)) * 1024 + h * 64;
#pragma unroll
    for (int nd = 0; nd < 8; nd++) {
        int col = nd * 8 + 2 * tig;
        float2 o0, o1;
        o0.x = __uint_as_float(f2tf(oacc[nd][0] * i0));
        o0.y = __uint_as_float(f2tf(oacc[nd][1] * i0));
        o1.x = __uint_as_float(f2tf(oacc[nd][2] * i1));
        o1.y = __uint_as_float(f2tf(oacc[nd][3] * i1));
        *(float2*)&ob[(size_t)g * 1024 + col] = o0;
        *(float2*)&ob[(size_t)(g + 8) * 1024 + col] = o1;
    }
}

// ---------------------------------------------------------------------------
extern "C" void kernel_launch(void* const* d_in, const int* in_sizes, int n_in,
                              void* d_out, int out_size)
{
    const float* x      = (const float*)d_in[0];
    const float* qkv_w  = (const float*)d_in[1];
    const float* qkv_b  = (const float*)d_in[2];
    const float* out_w  = (const float*)d_in[3];
    const float* out_b  = (const float*)d_in[4];
    float* out = (float*)d_out;

    float *qkv_buf, *attn_buf, *xtf, *wtf, *owtf;
    cudaGetSymbolAddress((void**)&qkv_buf, g_qkv);
    cudaGetSymbolAddress((void**)&attn_buf, g_attn);
    cudaGetSymbolAddress((void**)&xtf, g_xtf);
    cudaGetSymbolAddress((void**)&wtf, g_wtf);
    cudaGetSymbolAddress((void**)&owtf, g_owtf);

    const int M = BATCH * T_SEQ;   // 4096
    const int gemm_smem = 2 * BUFSZ * 4;

    cudaFuncSetAttribute(gemm_tf32, cudaFuncAttributeMaxDynamicSharedMemorySize,
                         gemm_smem);

    // 0) pre-round inputs to tf32
    round_tf32<<<(M * DMODEL / 4 + 255) / 256, 256>>>(x, xtf, M * DMODEL / 4);
    round_tf32<<<(DMODEL * 3 * DMODEL / 4 + 255) / 256, 256>>>(qkv_w, wtf, DMODEL * 3 * DMODEL / 4);
    round_tf32<<<(DMODEL * DMODEL / 4 + 255) / 256, 256>>>(out_w, owtf, DMODEL * DMODEL / 4);

    // 1) QKV GEMM + bias
    gemm_tf32<<<dim3(3 * DMODEL / 128, M / 128), 256, gemm_smem>>>(
        xtf, wtf, qkv_b, qkv_buf, M, 3 * DMODEL, DMODEL);

    // 2) RoPE (writes q,k rounded; rounds v)
    rope_kernel<<<(BATCH * T_SEQ * NHEAD) / 256, 256>>>();

    // 3) Flash attention
    flash_tf32<<<dim3(T_SEQ / 64, NHEAD, BATCH), 128>>>();

    // 4) Output GEMM + bias
    gemm_tf32<<<dim3(DMODEL / 128, M / 128), 256, gemm_smem>>>(
        attn_buf, owtf, out_b, out, M, DMODEL, DMODEL);
}

// round 7
// speedup vs baseline: 7.8951x; 1.8915x over previous
#include <cuda_runtime.h>
#include <cuda_fp16.h>
#include <math.h>
#include <stdint.h>

#define T_SEQ 2048
#define BATCH 2
#define NHEAD 16
#define HDIM 64
#define DMODEL 1024

__device__ float  g_qkv[BATCH * T_SEQ * 3 * DMODEL];    // fp32 GEMM output
__device__ __half g_qkvh[BATCH * T_SEQ * 3 * DMODEL];   // half q(scaled,rot), k(rot), v
__device__ __half g_attnh[BATCH * T_SEQ * DMODEL];      // flash output, half
__device__ __half g_xh[BATCH * T_SEQ * DMODEL];         // x as half
__device__ __half g_wth[3 * DMODEL * DMODEL];           // qkv_w^T [3D, D] half
__device__ __half g_owth[DMODEL * DMODEL];              // out_w^T [D, D] half

// ---------------------------------------------------------------------------
__device__ __forceinline__ void mma_f16(float* d, const uint32_t* a, const uint32_t* b) {
    asm volatile(
        "mma.sync.aligned.m16n8k16.row.col.f32.f16.f16.f32 "
        "{%0,%1,%2,%3}, {%4,%5,%6,%7}, {%8,%9}, {%0,%1,%2,%3};"
        : "+f"(d[0]), "+f"(d[1]), "+f"(d[2]), "+f"(d[3])
        : "r"(a[0]), "r"(a[1]), "r"(a[2]), "r"(a[3]), "r"(b[0]), "r"(b[1]));
}

__device__ __forceinline__ void ldsm4(uint32_t& r0, uint32_t& r1, uint32_t& r2,
                                      uint32_t& r3, uint32_t a) {
    asm volatile("ldmatrix.sync.aligned.m8n8.x4.shared.b16 {%0,%1,%2,%3}, [%4];"
                 : "=r"(r0), "=r"(r1), "=r"(r2), "=r"(r3) : "r"(a));
}
__device__ __forceinline__ void ldsm4t(uint32_t& r0, uint32_t& r1, uint32_t& r2,
                                       uint32_t& r3, uint32_t a) {
    asm volatile("ldmatrix.sync.aligned.m8n8.x4.trans.shared.b16 {%0,%1,%2,%3}, [%4];"
                 : "=r"(r0), "=r"(r1), "=r"(r2), "=r"(r3) : "r"(a));
}

__device__ __forceinline__ void cpa16(uint32_t saddr, const void* g) {
    asm volatile("cp.async.cg.shared.global [%0], [%1], 16;" :: "r"(saddr), "l"(g));
}
__device__ __forceinline__ void cpa_commit() {
    asm volatile("cp.async.commit_group;");
}
__device__ __forceinline__ void cpa_wait1() {
    asm volatile("cp.async.wait_group 1;" ::: "memory");
}

__device__ __forceinline__ uint32_t h2u(__half2 h) {
    return *reinterpret_cast<uint32_t*>(&h);
}

// ---------------------------------------------------------------------------
// Pre-passes.
// ---------------------------------------------------------------------------
__global__ void conv_half(const float* __restrict__ src, __half* __restrict__ dst, int n4)
{
    int i = blockIdx.x * blockDim.x + threadIdx.x;
    if (i < n4) {
        float4 v = ((const float4*)src)[i];
        __half2 a = __floats2half2_rn(v.x, v.y);
        __half2 b = __floats2half2_rn(v.z, v.w);
        uint2 o = make_uint2(h2u(a), h2u(b));
        ((uint2*)dst)[i] = o;
    }
}

// src [R][C] fp32 row-major -> dst [C][R] half row-major.
__global__ void transpose_half(const float* __restrict__ src, __half* __restrict__ dst,
                               int R, int C)
{
    __shared__ float tile[32][33];
    int c0 = blockIdx.x * 32, r0 = blockIdx.y * 32;
    int x = threadIdx.x, y = threadIdx.y;   // block (32, 8)
#pragma unroll
    for (int i = 0; i < 32; i += 8)
        tile[y + i][x] = src[(size_t)(r0 + y + i) * C + c0 + x];
    __syncthreads();
#pragma unroll
    for (int i = 0; i < 32; i += 8)
        dst[(size_t)(c0 + y + i) * R + r0 + x] = __float2half_rn(tile[x][y + i]);
}

// ---------------------------------------------------------------------------
// fp16 tensor GEMM: C[M,N] = A[M,K] * Bt[N,K]^T + bias.
// 128x128x64 tiles, 256 thr (8 warps, warp tile 32x64), cp.async double-buf,
// ldmatrix fragments from pad-72-half rows (bank-conflict-free).
// ---------------------------------------------------------------------------
#define GH_BYTES (128 * 72 * 2)          // one tile (A or B): 18432 B
#define GEMM_SMEM (4 * GH_BYTES)         // 2 buffers x (A+B) = 73728 B

__global__ __launch_bounds__(256, 2) void gemm_h(
    const __half* __restrict__ A, const __half* __restrict__ Bt,
    const float* __restrict__ bias, float* __restrict__ C,
    int M, int N, int K)
{
    extern __shared__ __half hsm[];

    int tid = threadIdx.x;
    int lane = tid & 31, warp = tid >> 5;
    int g = lane >> 2, tig = lane & 3;
    int bm = blockIdx.y * 128, bn = blockIdx.x * 128;
    int wm = warp & 3, wn = warp >> 2;

    float acc[2][8][4];
#pragma unroll
    for (int i = 0; i < 2; i++)
#pragma unroll
        for (int j = 0; j < 8; j++)
#pragma unroll
            for (int e = 0; e < 4; e++) acc[i][j][e] = 0.f;

    uint32_t base = (uint32_t)__cvta_generic_to_shared(hsm);

    auto issue = [&](int kc, int buf) {
        uint32_t ab = base + buf * 2 * GH_BYTES;
        uint32_t bb = ab + GH_BYTES;
#pragma unroll
        for (int i = 0; i < 4; i++) {
            int c = tid + i * 256;              // 0..1023
            int row = c >> 3, cc = c & 7;
            cpa16(ab + row * 144 + cc * 16, A + (size_t)(bm + row) * K + kc * 64 + cc * 8);
            cpa16(bb + row * 144 + cc * 16, Bt + (size_t)(bn + row) * K + kc * 64 + cc * 8);
        }
        cpa_commit();
    };

    int nk = K / 64;
    issue(0, 0);

    // precomputed ldmatrix lane offsets
    int a_r = (lane & 7) + ((lane >> 3) & 1) * 8;   // row within 16
    int a_c = ((lane >> 4) & 1) * 8;                // col offset
    int b_r = (lane & 7) + ((lane >> 4) & 1) * 8;   // n within 16
    int b_c = ((lane >> 3) & 1) * 8;                // k offset

    for (int kt = 0; kt < nk; kt++) {
        if (kt + 1 < nk) issue(kt + 1, (kt + 1) & 1);
        else cpa_commit();
        cpa_wait1();
        __syncthreads();

        uint32_t ab = base + (kt & 1) * 2 * GH_BYTES;
        uint32_t bb = ab + GH_BYTES;

#pragma unroll
        for (int ks = 0; ks < 4; ks++) {
            uint32_t af[2][4];
#pragma unroll
            for (int mt = 0; mt < 2; mt++) {
                int r = wm * 32 + mt * 16 + a_r;
                int c = ks * 16 + a_c;
                ldsm4(af[mt][0], af[mt][1], af[mt][2], af[mt][3],
                      ab + (uint32_t)(r * 144 + c * 2));
            }
#pragma unroll
            for (int nq = 0; nq < 4; nq++) {
                int n = wn * 64 + nq * 16 + b_r;
                int c = ks * 16 + b_c;
                uint32_t b0, b1, b2, b3;
                ldsm4(b0, b1, b2, b3, bb + (uint32_t)(n * 144 + c * 2));
                uint32_t bfa[2] = {b0, b1}, bfb[2] = {b2, b3};
#pragma unroll
                for (int mt = 0; mt < 2; mt++) {
                    mma_f16(acc[mt][2 * nq], af[mt], bfa);
                    mma_f16(acc[mt][2 * nq + 1], af[mt], bfb);
                }
            }
        }
        __syncthreads();
    }

#pragma unroll
    for (int mt = 0; mt < 2; mt++) {
        int row = bm + wm * 32 + mt * 16 + g;
#pragma unroll
        for (int nt = 0; nt < 8; nt++) {
            int col = bn + wn * 64 + nt * 8 + tig * 2;
            float bx = bias[col], by = bias[col + 1];
            float2 o0 = make_float2(acc[mt][nt][0] + bx, acc[mt][nt][1] + by);
            float2 o1 = make_float2(acc[mt][nt][2] + bx, acc[mt][nt][3] + by);
            *(float2*)(C + (size_t)row * N + col) = o0;
            *(float2*)(C + (size_t)(row + 8) * N + col) = o1;
        }
    }
}

// ---------------------------------------------------------------------------
// RoPE (reference's scrambled indexing). Reads fp32 qkv, writes half q
// (pre-scaled by 1/8), half k, half v into g_qkvh.
// ---------------------------------------------------------------------------
__device__ __forceinline__ float invfreq(int i) {
    return exp2f(-(float)i * (13.287712379549449f / 32.0f));
}
__device__ __forceinline__ float rope_val(float tf, int i) {
    if (i < 32) return sinf(tf * invfreq(i));
    return cosf(tf * invfreq(i - 32));
}

__global__ void rope_kernel()
{
    int idx = blockIdx.x * blockDim.x + threadIdx.x;
    int h = idx % NHEAD;
    int t = (idx / NHEAD) % T_SEQ;
    int b = idx / (NHEAD * T_SEQ);
    float tf = (float)t;

    float sv[32], cv[32];
#pragma unroll
    for (int j = 0; j < 32; j++) {
        sv[j] = rope_val(tf, 2 * j);
        cv[j] = rope_val(tf, 2 * j + 1);
    }

    size_t off = ((size_t)(b * T_SEQ + t)) * (3 * DMODEL) + h * HDIM;
    const float* base = g_qkv + off;
    __half* hbase = g_qkvh + off;

#pragma unroll
    for (int s = 0; s < 2; s++) {            // q (s=0, scaled), k (s=1)
        const float* p = base + s * DMODEL;
        __half* ph = hbase + s * DMODEL;
        float sc = (s == 0) ? 0.125f : 1.0f;
        float x[64];
#pragma unroll
        for (int d = 0; d < 64; d += 4) {
            float4 v = *(const float4*)(p + d);
            x[d] = v.x; x[d + 1] = v.y; x[d + 2] = v.z; x[d + 3] = v.w;
        }
        float o[64];
#pragma unroll
        for (int j = 0; j < 32; j++) {
            o[j]      = (x[2 * j] * cv[j] - x[2 * j + 1] * sv[j]) * sc;
            o[32 + j] = (x[2 * j] * sv[j] + x[2 * j + 1] * cv[j]) * sc;
        }
#pragma unroll
        for (int d = 0; d < 64; d += 4) {
            __half2 h0 = __floats2half2_rn(o[d], o[d + 1]);
            __half2 h1 = __floats2half2_rn(o[d + 2], o[d + 3]);
            uint2 u = make_uint2(h2u(h0), h2u(h1));
            *(uint2*)(ph + d) = u;
        }
    }
    // v: convert only
    const float* pv = base + 2 * DMODEL;
    __half* pvh = hbase + 2 * DMODEL;
#pragma unroll
    for (int d = 0; d < 64; d += 4) {
        float4 v = *(const float4*)(pv + d);
        __half2 h0 = __floats2half2_rn(v.x, v.y);
        __half2 h1 = __floats2half2_rn(v.z, v.w);
        uint2 u = make_uint2(h2u(h0), h2u(h1));
        *(uint2*)(pvh + d) = u;
    }
}

// ---------------------------------------------------------------------------
// Flash attention, fp16 mma. 4 warps, 64 q/block (16/warp), 64-key tiles,
// cp.async double-buffered K/V, ldmatrix K (B-frags) / V (.trans),
// P repacked in registers (no shared round-trip).
// ---------------------------------------------------------------------------
__global__ __launch_bounds__(128) void flash_h16()
{
    int qt = (gridDim.x - 1) - blockIdx.x;
    int h = blockIdx.y, b = blockIdx.z;
    int tid = threadIdx.x, warp = tid >> 5, lane = tid & 31;
    int g = lane >> 2, tig = lane & 3;
    int q0 = qt * 64 + warp * 16;

    __shared__ __half Ks[2][64 * 72];
    __shared__ __half Vs[2][64 * 72];

    uint32_t kbase = (uint32_t)__cvta_generic_to_shared(&Ks[0][0]);
    uint32_t vbase = (uint32_t)__cvta_generic_to_shared(&Vs[0][0]);

    auto issue = [&](int k0, int buf) {
        uint32_t kb = kbase + buf * (64 * 72 * 2);
        uint32_t vb = vbase + buf * (64 * 72 * 2);
#pragma unroll
        for (int i = 0; i < 4; i++) {
            int c = tid + i * 128;              // 0..511
            int row = c >> 3, cc = c & 7;
            const __half* kg = g_qkvh + ((size_t)(b * T_SEQ + k0 + row)) * 3072
                               + 1024 + h * 64 + cc * 8;
            cpa16(kb + row * 144 + cc * 16, kg);
            cpa16(vb + row * 144 + cc * 16, kg + 1024);
        }
        cpa_commit();
    };

    // Q fragments (q pre-scaled in rope): qf[ks][4]
    uint32_t qf[4][4];
    {
        const __half* qb = g_qkvh + ((size_t)(b * T_SEQ + q0)) * 3072 + h * 64;
        const __half* r0 = qb + (size_t)g * 3072;
        const __half* r1 = qb + (size_t)(g + 8) * 3072;
#pragma unroll
        for (int ks = 0; ks < 4; ks++) {
            qf[ks][0] = *(const uint32_t*)(r0 + ks * 16 + 2 * tig);
            qf[ks][1] = *(const uint32_t*)(r1 + ks * 16 + 2 * tig);
            qf[ks][2] = *(const uint32_t*)(r0 + ks * 16 + 8 + 2 * tig);
            qf[ks][3] = *(const uint32_t*)(r1 + ks * 16 + 8 + 2 * tig);
        }
    }

    float oacc[8][4];
#pragma unroll
    for (int i = 0; i < 8; i++)
#pragma unroll
        for (int e = 0; e < 4; e++) oacc[i][e] = 0.f;
    float m0 = -INFINITY, m1 = -INFINITY, l0 = 0.f, l1 = 0.f;

    // ldmatrix lane offsets
    int kb_r = (lane & 7) + ((lane >> 4) & 1) * 8;   // n (key) within 16
    int kb_c = ((lane >> 3) & 1) * 8;                // k (d) offset
    int vt_r = (lane & 7) + ((lane >> 3) & 1) * 8;   // key within 16
    int vt_c = ((lane >> 4) & 1) * 8;                // d offset

    int ntiles = qt + 1;
    issue(0, 0);

    for (int kt = 0; kt < ntiles; kt++) {
        int k0 = kt * 64;
        if (kt + 1 < ntiles) issue((kt + 1) * 64, (kt + 1) & 1);
        else cpa_commit();
        cpa_wait1();
        __syncthreads();

        uint32_t kb = kbase + (kt & 1) * (64 * 72 * 2);
        uint32_t vb = vbase + (kt & 1) * (64 * 72 * 2);

        // ---- S = Q K^T (16q x 64keys per warp)
        float sacc[8][4];
#pragma unroll
        for (int nt = 0; nt < 8; nt++)
#pragma unroll
            for (int e = 0; e < 4; e++) sacc[nt][e] = 0.f;
#pragma unroll
        for (int ks = 0; ks < 4; ks++) {
#pragma unroll
            for (int nq = 0; nq < 4; nq++) {
                int n = nq * 16 + kb_r;
                int c = ks * 16 + kb_c;
                uint32_t b0, b1, b2, b3;
                ldsm4(b0, b1, b2, b3, kb + (uint32_t)(n * 144 + c * 2));
                uint32_t bfa[2] = {b0, b1}, bfb[2] = {b2, b3};
                mma_f16(sacc[2 * nq], qf[ks], bfa);
                mma_f16(sacc[2 * nq + 1], qf[ks], bfb);
            }
        }

        // ---- causal mask (diagonal block only)
        if (kt == qt) {
#pragma unroll
            for (int nt = 0; nt < 8; nt++) {
                int key = k0 + nt * 8 + 2 * tig;
                if (key     > q0 + g)     sacc[nt][0] = -INFINITY;
                if (key + 1 > q0 + g)     sacc[nt][1] = -INFINITY;
                if (key     > q0 + 8 + g) sacc[nt][2] = -INFINITY;
                if (key + 1 > q0 + 8 + g) sacc[nt][3] = -INFINITY;
            }
        }

        // ---- online softmax
        float mx0 = -INFINITY, mx1 = -INFINITY;
#pragma unroll
        for (int nt = 0; nt < 8; nt++) {
            mx0 = fmaxf(mx0, fmaxf(sacc[nt][0], sacc[nt][1]));
            mx1 = fmaxf(mx1, fmaxf(sacc[nt][2], sacc[nt][3]));
        }
        mx0 = fmaxf(mx0, __shfl_xor_sync(0xffffffffu, mx0, 1));
        mx0 = fmaxf(mx0, __shfl_xor_sync(0xffffffffu, mx0, 2));
        mx1 = fmaxf(mx1, __shfl_xor_sync(0xffffffffu, mx1, 1));
        mx1 = fmaxf(mx1, __shfl_xor_sync(0xffffffffu, mx1, 2));

        float mn0 = fmaxf(m0, mx0), mn1 = fmaxf(m1, mx1);
        float a0 = __expf(m0 - mn0), a1 = __expf(m1 - mn1);
        m0 = mn0; m1 = mn1;
        l0 *= a0; l1 *= a1;
#pragma unroll
        for (int nd = 0; nd < 8; nd++) {
            oacc[nd][0] *= a0; oacc[nd][1] *= a0;
            oacc[nd][2] *= a1; oacc[nd][3] *= a1;
        }

        // ---- P = exp(S - m) in registers (half2-packed A-frags)
        uint32_t pf[8][2];          // pf[nt][0] = rows g pair, [1] = rows g+8 pair
#pragma unroll
        for (int nt = 0; nt < 8; nt++) {
            float p0 = __expf(sacc[nt][0] - mn0);
            float p1 = __expf(sacc[nt][1] - mn0);
            float p2 = __expf(sacc[nt][2] - mn1);
            float p3 = __expf(sacc[nt][3] - mn1);
            l0 += p0 + p1; l1 += p2 + p3;
            pf[nt][0] = h2u(__floats2half2_rn(p0, p1));
            pf[nt][1] = h2u(__floats2half2_rn(p2, p3));
        }

        // ---- O += P V
#pragma unroll
        for (int kk = 0; kk < 4; kk++) {      // key16 steps
            uint32_t af[4] = {pf[2 * kk][0], pf[2 * kk][1],
                              pf[2 * kk + 1][0], pf[2 * kk + 1][1]};
#pragma unroll
            for (int dq = 0; dq < 4; dq++) {  // d16 blocks
                int key = kk * 16 + vt_r;
                int dc = dq * 16 + vt_c;
                uint32_t b0, b1, b2, b3;
                ldsm4t(b0, b1, b2, b3, vb + (uint32_t)(key * 144 + dc * 2));
                uint32_t bfa[2] = {b0, b1}, bfb[2] = {b2, b3};
                mma_f16(oacc[2 * dq], af, bfa);
                mma_f16(oacc[2 * dq + 1], af, bfb);
            }
        }
        __syncthreads();
    }

    l0 += __shfl_xor_sync(0xffffffffu, l0, 1);
    l0 += __shfl_xor_sync(0xffffffffu, l0, 2);
    l1 += __shfl_xor_sync(0xffffffffu, l1, 1);
    l1 += __shfl_xor_sync(0xffffffffu, l1, 2);
    float i0 = 1.f / l0, i1 = 1.f / l1;

    __half* ob = g_attnh + ((size_t)(b * T_SEQ + q0)) * 1024 + h * 64;
#pragma unroll
    for (int nd = 0; nd < 8; nd++) {
        int col = nd * 8 + 2 * tig;
        __half2 o0 = __floats2half2_rn(oacc[nd][0] * i0, oacc[nd][1] * i0);
        __half2 o1 = __floats2half2_rn(oacc[nd][2] * i1, oacc[nd][3] * i1);
        *(uint32_t*)(ob + (size_t)g * 1024 + col) = h2u(o0);
        *(uint32_t*)(ob + (size_t)(g + 8) * 1024 + col) = h2u(o1);
    }
}

// ---------------------------------------------------------------------------
extern "C" void kernel_launch(void* const* d_in, const int* in_sizes, int n_in,
                              void* d_out, int out_size)
{
    const float* x      = (const float*)d_in[0];
    const float* qkv_w  = (const float*)d_in[1];
    const float* qkv_b  = (const float*)d_in[2];
    const float* out_w  = (const float*)d_in[3];
    const float* out_b  = (const float*)d_in[4];
    float* out = (float*)d_out;

    float* qkv_buf;
    __half *xh, *wth, *owth, *attnh;
    cudaGetSymbolAddress((void**)&qkv_buf, g_qkv);
    cudaGetSymbolAddress((void**)&xh, g_xh);
    cudaGetSymbolAddress((void**)&wth, g_wth);
    cudaGetSymbolAddress((void**)&owth, g_owth);
    cudaGetSymbolAddress((void**)&attnh, g_attnh);

    const int M = BATCH * T_SEQ;   // 4096

    cudaFuncSetAttribute(gemm_h, cudaFuncAttributeMaxDynamicSharedMemorySize,
                         GEMM_SMEM);

    // 0) convert x to half; transpose weights to [N,K] half
    conv_half<<<(M * DMODEL / 4 + 255) / 256, 256>>>(x, xh, M * DMODEL / 4);
    transpose_half<<<dim3(3 * DMODEL / 32, DMODEL / 32), dim3(32, 8)>>>(
        qkv_w, wth, DMODEL, 3 * DMODEL);
    transpose_half<<<dim3(DMODEL / 32, DMODEL / 32), dim3(32, 8)>>>(
        out_w, owth, DMODEL, DMODEL);

    // 1) QKV GEMM + bias (fp16 tensor, fp32 out)
    gemm_h<<<dim3(3 * DMODEL / 128, M / 128), 256, GEMM_SMEM>>>(
        xh, wth, qkv_b, qkv_buf, M, 3 * DMODEL, DMODEL);

    // 2) RoPE -> half q(scaled)/k/v
    rope_kernel<<<(BATCH * T_SEQ * NHEAD) / 256, 256>>>();

    // 3) Flash attention (fp16) -> g_attnh
    flash_h16<<<dim3(T_SEQ / 64, NHEAD, BATCH), 128>>>();

    // 4) Output GEMM + bias
    gemm_h<<<dim3(DMODEL / 128, M / 128), 256, GEMM_SMEM>>>(
        attnh, owth, out_b, out, M, DMODEL, DMODEL);
}

// round 9
// speedup vs baseline: 8.6207x; 1.0919x over previous
#include <cuda_runtime.h>
#include <cuda_fp16.h>
#include <math.h>
#include <stdint.h>

#define T_SEQ 2048
#define BATCH 2
#define NHEAD 16
#define HDIM 64
#define DMODEL 1024

__device__ float  g_qkv[BATCH * T_SEQ * 3 * DMODEL];    // fp32 GEMM output
__device__ __half g_qkvh[BATCH * T_SEQ * 3 * DMODEL];   // half q(scaled,rot), k(rot), v
__device__ __half g_attnh[BATCH * T_SEQ * DMODEL];      // flash output, half
__device__ __half g_xh[BATCH * T_SEQ * DMODEL];         // x as half
__device__ __half g_wth[3 * DMODEL * DMODEL];           // qkv_w^T [3D, D] half
__device__ __half g_owth[DMODEL * DMODEL];              // out_w^T [D, D] half

// ---------------------------------------------------------------------------
__device__ __forceinline__ void mma_f16(float* d, const uint32_t* a, const uint32_t* b) {
    asm volatile(
        "mma.sync.aligned.m16n8k16.row.col.f32.f16.f16.f32 "
        "{%0,%1,%2,%3}, {%4,%5,%6,%7}, {%8,%9}, {%0,%1,%2,%3};"
        : "+f"(d[0]), "+f"(d[1]), "+f"(d[2]), "+f"(d[3])
        : "r"(a[0]), "r"(a[1]), "r"(a[2]), "r"(a[3]), "r"(b[0]), "r"(b[1]));
}

__device__ __forceinline__ void ldsm4(uint32_t& r0, uint32_t& r1, uint32_t& r2,
                                      uint32_t& r3, uint32_t a) {
    asm volatile("ldmatrix.sync.aligned.m8n8.x4.shared.b16 {%0,%1,%2,%3}, [%4];"
                 : "=r"(r0), "=r"(r1), "=r"(r2), "=r"(r3) : "r"(a));
}
__device__ __forceinline__ void ldsm4t(uint32_t& r0, uint32_t& r1, uint32_t& r2,
                                       uint32_t& r3, uint32_t a) {
    asm volatile("ldmatrix.sync.aligned.m8n8.x4.trans.shared.b16 {%0,%1,%2,%3}, [%4];"
                 : "=r"(r0), "=r"(r1), "=r"(r2), "=r"(r3) : "r"(a));
}

__device__ __forceinline__ void cpa16(uint32_t saddr, const void* g) {
    asm volatile("cp.async.cg.shared.global [%0], [%1], 16;" :: "r"(saddr), "l"(g));
}
__device__ __forceinline__ void cpa_commit() {
    asm volatile("cp.async.commit_group;");
}
__device__ __forceinline__ void cpa_wait1() {
    asm volatile("cp.async.wait_group 1;" ::: "memory");
}
__device__ __forceinline__ void cpa_wait_all() {
    asm volatile("cp.async.wait_all;" ::: "memory");
}

__device__ __forceinline__ uint32_t h2u(__half2 h) {
    return *reinterpret_cast<uint32_t*>(&h);
}

__device__ __forceinline__ float ex2(float x) {
    float y;
    asm("ex2.approx.f32 %0, %1;" : "=f"(y) : "f"(x));
    return y;
}

// ---------------------------------------------------------------------------
// Pre-passes.
// ---------------------------------------------------------------------------
__global__ void conv_half(const float* __restrict__ src, __half* __restrict__ dst, int n4)
{
    int i = blockIdx.x * blockDim.x + threadIdx.x;
    if (i < n4) {
        float4 v = ((const float4*)src)[i];
        __half2 a = __floats2half2_rn(v.x, v.y);
        __half2 b = __floats2half2_rn(v.z, v.w);
        uint2 o = make_uint2(h2u(a), h2u(b));
        ((uint2*)dst)[i] = o;
    }
}

// src [R][C] fp32 row-major -> dst [C][R] half row-major.
__global__ void transpose_half(const float* __restrict__ src, __half* __restrict__ dst,
                               int R, int C)
{
    __shared__ float tile[32][33];
    int c0 = blockIdx.x * 32, r0 = blockIdx.y * 32;
    int x = threadIdx.x, y = threadIdx.y;   // block (32, 8)
#pragma unroll
    for (int i = 0; i < 32; i += 8)
        tile[y + i][x] = src[(size_t)(r0 + y + i) * C + c0 + x];
    __syncthreads();
#pragma unroll
    for (int i = 0; i < 32; i += 8)
        dst[(size_t)(c0 + y + i) * R + r0 + x] = __float2half_rn(tile[x][y + i]);
}

// ---------------------------------------------------------------------------
// fp16 tensor GEMM: C[M,N] = A[M,K] * Bt[N,K]^T + bias.
// 128x128x64 tiles, 256 thr, 3-stage cp.async pipeline,
// XOR-swizzled SMEM (rows = 128B, no padding).
// ---------------------------------------------------------------------------
#define GT_BYTES (128 * 64 * 2)          // 16384 per tile
#define GSTAGE   (2 * GT_BYTES)          // A + B = 32768
#define GEMM_SMEM (3 * GSTAGE)           // 98304

__global__ __launch_bounds__(256, 2) void gemm_h(
    const __half* __restrict__ A, const __half* __restrict__ Bt,
    const float* __restrict__ bias, float* __restrict__ C,
    int M, int N, int K)
{
    extern __shared__ __half hsm[];

    int tid = threadIdx.x;
    int lane = tid & 31, warp = tid >> 5;
    int g = lane >> 2, tig = lane & 3;
    int bm = blockIdx.y * 128, bn = blockIdx.x * 128;
    int wm = warp & 3, wn = warp >> 2;

    float acc[2][8][4];
#pragma unroll
    for (int i = 0; i < 2; i++)
#pragma unroll
        for (int j = 0; j < 8; j++)
#pragma unroll
            for (int e = 0; e < 4; e++) acc[i][j][e] = 0.f;

    uint32_t base = (uint32_t)__cvta_generic_to_shared(hsm);

    auto issue = [&](int kc, int buf) {   // kc = K-tile index
        uint32_t ab = base + buf * GSTAGE;
        uint32_t bb = ab + GT_BYTES;
#pragma unroll
        for (int i = 0; i < 4; i++) {
            int c = tid + i * 256;              // 0..1023
            int row = c >> 3, cc = c & 7;
            uint32_t sw = (uint32_t)(row * 128 + ((cc ^ (row & 7)) << 4));
            cpa16(ab + sw, A + (size_t)(bm + row) * K + kc * 64 + cc * 8);
            cpa16(bb + sw, Bt + (size_t)(bn + row) * K + kc * 64 + cc * 8);
        }
        cpa_commit();
    };

    int nk = K / 64;
    issue(0, 0);
    issue(1, 1);

    // ldmatrix lane offsets
    int a_r = (lane & 7) + ((lane >> 3) & 1) * 8;
    int a_hi = (lane >> 4) & 1;
    int b_r = (lane & 7) + ((lane >> 4) & 1) * 8;
    int b_hi = (lane >> 3) & 1;

    for (int kt = 0; kt < nk; kt++) {
        cpa_wait1();
        __syncthreads();
        if (kt + 2 < nk) issue(kt + 2, (kt + 2) % 3);
        else cpa_commit();

        uint32_t ab = base + (kt % 3) * GSTAGE;
        uint32_t bb = ab + GT_BYTES;

#pragma unroll
        for (int ks = 0; ks < 4; ks++) {
            uint32_t af[2][4];
#pragma unroll
            for (int mt = 0; mt < 2; mt++) {
                int r = wm * 32 + mt * 16 + a_r;
                uint32_t addr = ab + r * 128 + (((ks * 2 + a_hi) ^ (r & 7)) << 4);
                ldsm4(af[mt][0], af[mt][1], af[mt][2], af[mt][3], addr);
            }
#pragma unroll
            for (int nq = 0; nq < 4; nq++) {
                int n = wn * 64 + nq * 16 + b_r;
                uint32_t addr = bb + n * 128 + (((ks * 2 + b_hi) ^ (n & 7)) << 4);
                uint32_t b0, b1, b2, b3;
                ldsm4(b0, b1, b2, b3, addr);
                uint32_t bfa[2] = {b0, b1}, bfb[2] = {b2, b3};
#pragma unroll
                for (int mt = 0; mt < 2; mt++) {
                    mma_f16(acc[mt][2 * nq], af[mt], bfa);
                    mma_f16(acc[mt][2 * nq + 1], af[mt], bfb);
                }
            }
        }
        __syncthreads();
    }
    cpa_wait_all();

#pragma unroll
    for (int mt = 0; mt < 2; mt++) {
        int row = bm + wm * 32 + mt * 16 + g;
#pragma unroll
        for (int nt = 0; nt < 8; nt++) {
            int col = bn + wn * 64 + nt * 8 + tig * 2;
            float bx = bias[col], by = bias[col + 1];
            float2 o0 = make_float2(acc[mt][nt][0] + bx, acc[mt][nt][1] + by);
            float2 o1 = make_float2(acc[mt][nt][2] + bx, acc[mt][nt][3] + by);
            *(float2*)(C + (size_t)row * N + col) = o0;
            *(float2*)(C + (size_t)(row + 8) * N + col) = o1;
        }
    }
}

// ---------------------------------------------------------------------------
// RoPE (reference's scrambled indexing). q is pre-scaled by 0.125*log2(e)
// so flash softmax can run in the exp2 domain.
// ---------------------------------------------------------------------------
__device__ __forceinline__ float invfreq(int i) {
    return exp2f(-(float)i * (13.287712379549449f / 32.0f));
}
__device__ __forceinline__ float rope_val(float tf, int i) {
    if (i < 32) return sinf(tf * invfreq(i));
    return cosf(tf * invfreq(i - 32));
}

__global__ void rope_kernel()
{
    int idx = blockIdx.x * blockDim.x + threadIdx.x;
    int h = idx % NHEAD;
    int t = (idx / NHEAD) % T_SEQ;
    int b = idx / (NHEAD * T_SEQ);
    float tf = (float)t;

    float sv[32], cv[32];
#pragma unroll
    for (int j = 0; j < 32; j++) {
        sv[j] = rope_val(tf, 2 * j);
        cv[j] = rope_val(tf, 2 * j + 1);
    }

    size_t off = ((size_t)(b * T_SEQ + t)) * (3 * DMODEL) + h * HDIM;
    const float* base = g_qkv + off;
    __half* hbase = g_qkvh + off;

#pragma unroll
    for (int s = 0; s < 2; s++) {            // q (s=0, scaled), k (s=1)
        const float* p = base + s * DMODEL;
        __half* ph = hbase + s * DMODEL;
        float sc = (s == 0) ? 0.125f * 1.4426950408889634f : 1.0f;
        float x[64];
#pragma unroll
        for (int d = 0; d < 64; d += 4) {
            float4 v = *(const float4*)(p + d);
            x[d] = v.x; x[d + 1] = v.y; x[d + 2] = v.z; x[d + 3] = v.w;
        }
        float o[64];
#pragma unroll
        for (int j = 0; j < 32; j++) {
            o[j]      = (x[2 * j] * cv[j] - x[2 * j + 1] * sv[j]) * sc;
            o[32 + j] = (x[2 * j] * sv[j] + x[2 * j + 1] * cv[j]) * sc;
        }
#pragma unroll
        for (int d = 0; d < 64; d += 4) {
            __half2 h0 = __floats2half2_rn(o[d], o[d + 1]);
            __half2 h1 = __floats2half2_rn(o[d + 2], o[d + 3]);
            uint2 u = make_uint2(h2u(h0), h2u(h1));
            *(uint2*)(ph + d) = u;
        }
    }
    const float* pv = base + 2 * DMODEL;
    __half* pvh = hbase + 2 * DMODEL;
#pragma unroll
    for (int d = 0; d < 64; d += 4) {
        float4 v = *(const float4*)(pv + d);
        __half2 h0 = __floats2half2_rn(v.x, v.y);
        __half2 h1 = __floats2half2_rn(v.z, v.w);
        uint2 u = make_uint2(h2u(h0), h2u(h1));
        *(uint2*)(pvh + d) = u;
    }
}

// ---------------------------------------------------------------------------
// Flash attention, fp16 mma, exp2-domain softmax, 3-stage cp.async pipeline,
// XOR-swizzled K/V tiles (64x64 half, rows = 128B).
// issue() takes a TILE INDEX (same convention as gemm_h) — R8's bug was
// passing a tile index into an absolute-offset parameter here.
// ---------------------------------------------------------------------------
#define FT_BYTES (64 * 64 * 2)           // 8192 per tile (K or V)
#define FSTAGE   (2 * FT_BYTES)          // 16384
#define FLASH_SMEM (3 * FSTAGE)          // 49152

__global__ __launch_bounds__(128) void flash_h16()
{
    extern __shared__ __half fsm[];

    int qt = (gridDim.x - 1) - blockIdx.x;
    int h = blockIdx.y, b = blockIdx.z;
    int tid = threadIdx.x, warp = tid >> 5, lane = tid & 31;
    int g = lane >> 2, tig = lane & 3;
    int q0 = qt * 64 + warp * 16;

    uint32_t base = (uint32_t)__cvta_generic_to_shared(fsm);

    auto issue = [&](int ktile, int buf) {   // ktile = 64-key tile index
        int k0 = ktile * 64;
        uint32_t kb = base + buf * FSTAGE;
        uint32_t vb = kb + FT_BYTES;
#pragma unroll
        for (int i = 0; i < 4; i++) {
            int c = tid + i * 128;              // 0..511
            int row = c >> 3, cc = c & 7;
            uint32_t sw = (uint32_t)(row * 128 + ((cc ^ (row & 7)) << 4));
            const __half* kg = g_qkvh + ((size_t)(b * T_SEQ + k0 + row)) * 3072
                               + 1024 + h * 64 + cc * 8;
            cpa16(kb + sw, kg);
            cpa16(vb + sw, kg + 1024);
        }
        cpa_commit();
    };

    // Q fragments (pre-scaled by 0.125*log2e in rope)
    uint32_t qf[4][4];
    {
        const __half* qb = g_qkvh + ((size_t)(b * T_SEQ + q0)) * 3072 + h * 64;
        const __half* r0 = qb + (size_t)g * 3072;
        const __half* r1 = qb + (size_t)(g + 8) * 3072;
#pragma unroll
        for (int ks = 0; ks < 4; ks++) {
            qf[ks][0] = *(const uint32_t*)(r0 + ks * 16 + 2 * tig);
            qf[ks][1] = *(const uint32_t*)(r1 + ks * 16 + 2 * tig);
            qf[ks][2] = *(const uint32_t*)(r0 + ks * 16 + 8 + 2 * tig);
            qf[ks][3] = *(const uint32_t*)(r1 + ks * 16 + 8 + 2 * tig);
        }
    }

    float oacc[8][4];
#pragma unroll
    for (int i = 0; i < 8; i++)
#pragma unroll
        for (int e = 0; e < 4; e++) oacc[i][e] = 0.f;
    float m0 = -INFINITY, m1 = -INFINITY, l0 = 0.f, l1 = 0.f;

    // ldmatrix lane offsets
    int kb_r = (lane & 7) + ((lane >> 4) & 1) * 8;
    int kb_hi = (lane >> 3) & 1;
    int vt_r = (lane & 7) + ((lane >> 3) & 1) * 8;
    int vt_hi = (lane >> 4) & 1;

    int ntiles = qt + 1;
    issue(0, 0);
    issue(1, 1);        // tile INDEX 1 (keys 64..127); unused if qt==0, in-bounds

    for (int kt = 0; kt < ntiles; kt++) {
        int k0 = kt * 64;
        cpa_wait1();
        __syncthreads();
        if (kt + 2 < ntiles) issue(kt + 2, (kt + 2) % 3);
        else cpa_commit();

        uint32_t kb = base + (kt % 3) * FSTAGE;
        uint32_t vb = kb + FT_BYTES;

        // ---- S = Q K^T (16q x 64keys per warp), log2-domain scores
        float sacc[8][4];
#pragma unroll
        for (int nt = 0; nt < 8; nt++)
#pragma unroll
            for (int e = 0; e < 4; e++) sacc[nt][e] = 0.f;
#pragma unroll
        for (int ks = 0; ks < 4; ks++) {
#pragma unroll
            for (int nq = 0; nq < 4; nq++) {
                int n = nq * 16 + kb_r;
                uint32_t addr = kb + n * 128 + (((ks * 2 + kb_hi) ^ (n & 7)) << 4);
                uint32_t b0, b1, b2, b3;
                ldsm4(b0, b1, b2, b3, addr);
                uint32_t bfa[2] = {b0, b1}, bfb[2] = {b2, b3};
                mma_f16(sacc[2 * nq], qf[ks], bfa);
                mma_f16(sacc[2 * nq + 1], qf[ks], bfb);
            }
        }

        // ---- causal mask (diagonal block only)
        if (kt == qt) {
#pragma unroll
            for (int nt = 0; nt < 8; nt++) {
                int key = k0 + nt * 8 + 2 * tig;
                if (key     > q0 + g)     sacc[nt][0] = -INFINITY;
                if (key + 1 > q0 + g)     sacc[nt][1] = -INFINITY;
                if (key     > q0 + 8 + g) sacc[nt][2] = -INFINITY;
                if (key + 1 > q0 + 8 + g) sacc[nt][3] = -INFINITY;
            }
        }

        // ---- online softmax (exp2 domain)
        float mx0 = -INFINITY, mx1 = -INFINITY;
#pragma unroll
        for (int nt = 0; nt < 8; nt++) {
            mx0 = fmaxf(mx0, fmaxf(sacc[nt][0], sacc[nt][1]));
            mx1 = fmaxf(mx1, fmaxf(sacc[nt][2], sacc[nt][3]));
        }
        mx0 = fmaxf(mx0, __shfl_xor_sync(0xffffffffu, mx0, 1));
        mx0 = fmaxf(mx0, __shfl_xor_sync(0xffffffffu, mx0, 2));
        mx1 = fmaxf(mx1, __shfl_xor_sync(0xffffffffu, mx1, 1));
        mx1 = fmaxf(mx1, __shfl_xor_sync(0xffffffffu, mx1, 2));

        float mn0 = fmaxf(m0, mx0), mn1 = fmaxf(m1, mx1);
        float a0 = ex2(m0 - mn0), a1 = ex2(m1 - mn1);
        m0 = mn0; m1 = mn1;
        l0 *= a0; l1 *= a1;
#pragma unroll
        for (int nd = 0; nd < 8; nd++) {
            oacc[nd][0] *= a0; oacc[nd][1] *= a0;
            oacc[nd][2] *= a1; oacc[nd][3] *= a1;
        }

        // ---- P = exp2(S - m) in registers
        uint32_t pf[8][2];
#pragma unroll
        for (int nt = 0; nt < 8; nt++) {
            float p0 = ex2(sacc[nt][0] - mn0);
            float p1 = ex2(sacc[nt][1] - mn0);
            float p2 = ex2(sacc[nt][2] - mn1);
            float p3 = ex2(sacc[nt][3] - mn1);
            l0 += p0 + p1; l1 += p2 + p3;
            pf[nt][0] = h2u(__floats2half2_rn(p0, p1));
            pf[nt][1] = h2u(__floats2half2_rn(p2, p3));
        }

        // ---- O += P V
#pragma unroll
        for (int kk = 0; kk < 4; kk++) {
            uint32_t af[4] = {pf[2 * kk][0], pf[2 * kk][1],
                              pf[2 * kk + 1][0], pf[2 * kk + 1][1]};
#pragma unroll
            for (int dq = 0; dq < 4; dq++) {
                int key = kk * 16 + vt_r;
                uint32_t addr = vb + key * 128 + (((dq * 2 + vt_hi) ^ (key & 7)) << 4);
                uint32_t b0, b1, b2, b3;
                ldsm4t(b0, b1, b2, b3, addr);
                uint32_t bfa[2] = {b0, b1}, bfb[2] = {b2, b3};
                mma_f16(oacc[2 * dq], af, bfa);
                mma_f16(oacc[2 * dq + 1], af, bfb);
            }
        }
        __syncthreads();
    }
    cpa_wait_all();

    l0 += __shfl_xor_sync(0xffffffffu, l0, 1);
    l0 += __shfl_xor_sync(0xffffffffu, l0, 2);
    l1 += __shfl_xor_sync(0xffffffffu, l1, 1);
    l1 += __shfl_xor_sync(0xffffffffu, l1, 2);
    float i0 = 1.f / l0, i1 = 1.f / l1;

    __half* ob = g_attnh + ((size_t)(b * T_SEQ + q0)) * 1024 + h * 64;
#pragma unroll
    for (int nd = 0; nd < 8; nd++) {
        int col = nd * 8 + 2 * tig;
        __half2 o0 = __floats2half2_rn(oacc[nd][0] * i0, oacc[nd][1] * i0);
        __half2 o1 = __floats2half2_rn(oacc[nd][2] * i1, oacc[nd][3] * i1);
        *(uint32_t*)(ob + (size_t)g * 1024 + col) = h2u(o0);
        *(uint32_t*)(ob + (size_t)(g + 8) * 1024 + col) = h2u(o1);
    }
}

// ---------------------------------------------------------------------------
extern "C" void kernel_launch(void* const* d_in, const int* in_sizes, int n_in,
                              void* d_out, int out_size)
{
    const float* x      = (const float*)d_in[0];
    const float* qkv_w  = (const float*)d_in[1];
    const float* qkv_b  = (const float*)d_in[2];
    const float* out_w  = (const float*)d_in[3];
    const float* out_b  = (const float*)d_in[4];
    float* out = (float*)d_out;

    float* qkv_buf;
    __half *xh, *wth, *owth, *attnh;
    cudaGetSymbolAddress((void**)&qkv_buf, g_qkv);
    cudaGetSymbolAddress((void**)&xh, g_xh);
    cudaGetSymbolAddress((void**)&wth, g_wth);
    cudaGetSymbolAddress((void**)&owth, g_owth);
    cudaGetSymbolAddress((void**)&attnh, g_attnh);

    const int M = BATCH * T_SEQ;   // 4096

    cudaFuncSetAttribute(gemm_h, cudaFuncAttributeMaxDynamicSharedMemorySize,
                         GEMM_SMEM);
    cudaFuncSetAttribute(flash_h16, cudaFuncAttributeMaxDynamicSharedMemorySize,
                         FLASH_SMEM);

    // 0) convert x to half; transpose weights to [N,K] half
    conv_half<<<(M * DMODEL / 4 + 255) / 256, 256>>>(x, xh, M * DMODEL / 4);
    transpose_half<<<dim3(3 * DMODEL / 32, DMODEL / 32), dim3(32, 8)>>>(
        qkv_w, wth, DMODEL, 3 * DMODEL);
    transpose_half<<<dim3(DMODEL / 32, DMODEL / 32), dim3(32, 8)>>>(
        out_w, owth, DMODEL, DMODEL);

    // 1) QKV GEMM + bias (fp16 tensor, fp32 out)
    gemm_h<<<dim3(3 * DMODEL / 128, M / 128), 256, GEMM_SMEM>>>(
        xh, wth, qkv_b, qkv_buf, M, 3 * DMODEL, DMODEL);

    // 2) RoPE -> half q(scaled)/k/v
    rope_kernel<<<(BATCH * T_SEQ * NHEAD) / 256, 256>>>();

    // 3) Flash attention (fp16, exp2 softmax) -> g_attnh
    flash_h16<<<dim3(T_SEQ / 64, NHEAD, BATCH), 128, FLASH_SMEM>>>();

    // 4) Output GEMM + bias
    gemm_h<<<dim3(DMODEL / 128, M / 128), 256, GEMM_SMEM>>>(
        attnh, owth, out_b, out, M, DMODEL, DMODEL);
}

// round 11
// speedup vs baseline: 8.6828x; 1.0072x over previous
#include <cuda_runtime.h>
#include <cuda_fp16.h>
#include <math.h>
#include <stdint.h>

#define T_SEQ 2048
#define BATCH 2
#define NHEAD 16
#define HDIM 64
#define DMODEL 1024

__device__ float  g_qkv[BATCH * T_SEQ * 3 * DMODEL];    // fp32 GEMM output
__device__ __half g_qkvh[BATCH * T_SEQ * 3 * DMODEL];   // half q(scaled,rot), k(rot), v
__device__ __half g_attnh[BATCH * T_SEQ * DMODEL];      // flash output, half
__device__ __half g_xh[BATCH * T_SEQ * DMODEL];         // x as half
__device__ __half g_wth[3 * DMODEL * DMODEL];           // qkv_w^T [3D, D] half
__device__ __half g_owth[DMODEL * DMODEL];              // out_w^T [D, D] half

// ---------------------------------------------------------------------------
__device__ __forceinline__ void mma_f16(float* d, const uint32_t* a, const uint32_t* b) {
    asm volatile(
        "mma.sync.aligned.m16n8k16.row.col.f32.f16.f16.f32 "
        "{%0,%1,%2,%3}, {%4,%5,%6,%7}, {%8,%9}, {%0,%1,%2,%3};"
        : "+f"(d[0]), "+f"(d[1]), "+f"(d[2]), "+f"(d[3])
        : "r"(a[0]), "r"(a[1]), "r"(a[2]), "r"(a[3]), "r"(b[0]), "r"(b[1]));
}

__device__ __forceinline__ void ldsm4(uint32_t& r0, uint32_t& r1, uint32_t& r2,
                                      uint32_t& r3, uint32_t a) {
    asm volatile("ldmatrix.sync.aligned.m8n8.x4.shared.b16 {%0,%1,%2,%3}, [%4];"
                 : "=r"(r0), "=r"(r1), "=r"(r2), "=r"(r3) : "r"(a));
}
__device__ __forceinline__ void ldsm4t(uint32_t& r0, uint32_t& r1, uint32_t& r2,
                                       uint32_t& r3, uint32_t a) {
    asm volatile("ldmatrix.sync.aligned.m8n8.x4.trans.shared.b16 {%0,%1,%2,%3}, [%4];"
                 : "=r"(r0), "=r"(r1), "=r"(r2), "=r"(r3) : "r"(a));
}

__device__ __forceinline__ void cpa16(uint32_t saddr, const void* g) {
    asm volatile("cp.async.cg.shared.global [%0], [%1], 16;" :: "r"(saddr), "l"(g));
}
__device__ __forceinline__ void cpa_commit() {
    asm volatile("cp.async.commit_group;");
}
__device__ __forceinline__ void cpa_wait1() {
    asm volatile("cp.async.wait_group 1;" ::: "memory");
}
__device__ __forceinline__ void cpa_wait_all() {
    asm volatile("cp.async.wait_all;" ::: "memory");
}

__device__ __forceinline__ uint32_t h2u(__half2 h) {
    return *reinterpret_cast<uint32_t*>(&h);
}

__device__ __forceinline__ float ex2(float x) {
    float y;
    asm("ex2.approx.f32 %0, %1;" : "=f"(y) : "f"(x));
    return y;
}

// ---------------------------------------------------------------------------
// Pre-passes.
// ---------------------------------------------------------------------------
__global__ void conv_half(const float* __restrict__ src, __half* __restrict__ dst, int n4)
{
    int i = blockIdx.x * blockDim.x + threadIdx.x;
    if (i < n4) {
        float4 v = ((const float4*)src)[i];
        __half2 a = __floats2half2_rn(v.x, v.y);
        __half2 b = __floats2half2_rn(v.z, v.w);
        uint2 o = make_uint2(h2u(a), h2u(b));
        ((uint2*)dst)[i] = o;
    }
}

// src [R][C] fp32 row-major -> dst [C][R] half row-major.
__global__ void transpose_half(const float* __restrict__ src, __half* __restrict__ dst,
                               int R, int C)
{
    __shared__ float tile[32][33];
    int c0 = blockIdx.x * 32, r0 = blockIdx.y * 32;
    int x = threadIdx.x, y = threadIdx.y;   // block (32, 8)
#pragma unroll
    for (int i = 0; i < 32; i += 8)
        tile[y + i][x] = src[(size_t)(r0 + y + i) * C + c0 + x];
    __syncthreads();
#pragma unroll
    for (int i = 0; i < 32; i += 8)
        dst[(size_t)(c0 + y + i) * R + r0 + x] = __float2half_rn(tile[x][y + i]);
}

// ---------------------------------------------------------------------------
// fp16 tensor GEMM: C[M,N] = A[M,K] * Bt[N,K]^T + bias.
// 128x128x64 tiles, 256 thr, 3-stage cp.async pipeline, ONE barrier per iter.
// Ordering per iter: wait1 -> barrier -> issue(kt+2) -> compute(kt).
// The barrier both publishes tile kt and proves compute(kt-1) finished in all
// warps before issue(kt+2) overwrites buffer (kt-1)%3  (R10's race fixed).
// ---------------------------------------------------------------------------
#define GT_BYTES (128 * 64 * 2)          // 16384 per tile
#define GSTAGE   (2 * GT_BYTES)          // A + B = 32768
#define GEMM_SMEM (3 * GSTAGE)           // 98304

__global__ __launch_bounds__(256, 2) void gemm_h(
    const __half* __restrict__ A, const __half* __restrict__ Bt,
    const float* __restrict__ bias, float* __restrict__ C,
    int M, int N, int K)
{
    extern __shared__ __half hsm[];

    int tid = threadIdx.x;
    int lane = tid & 31, warp = tid >> 5;
    int g = lane >> 2, tig = lane & 3;
    int bm = blockIdx.y * 128, bn = blockIdx.x * 128;
    int wm = warp & 3, wn = warp >> 2;

    float acc[2][8][4];
#pragma unroll
    for (int i = 0; i < 2; i++)
#pragma unroll
        for (int j = 0; j < 8; j++)
#pragma unroll
            for (int e = 0; e < 4; e++) acc[i][j][e] = 0.f;

    uint32_t base = (uint32_t)__cvta_generic_to_shared(hsm);

    auto issue = [&](int kc, int buf) {   // kc = K-tile index
        uint32_t ab = base + buf * GSTAGE;
        uint32_t bb = ab + GT_BYTES;
#pragma unroll
        for (int i = 0; i < 4; i++) {
            int c = tid + i * 256;              // 0..1023
            int row = c >> 3, cc = c & 7;
            uint32_t sw = (uint32_t)(row * 128 + ((cc ^ (row & 7)) << 4));
            cpa16(ab + sw, A + (size_t)(bm + row) * K + kc * 64 + cc * 8);
            cpa16(bb + sw, Bt + (size_t)(bn + row) * K + kc * 64 + cc * 8);
        }
        cpa_commit();
    };

    int nk = K / 64;
    issue(0, 0);
    issue(1, 1);

    // ldmatrix lane offsets
    int a_r = (lane & 7) + ((lane >> 3) & 1) * 8;
    int a_hi = (lane >> 4) & 1;
    int b_r = (lane & 7) + ((lane >> 4) & 1) * 8;
    int b_hi = (lane >> 3) & 1;

    for (int kt = 0; kt < nk; kt++) {
        cpa_wait1();                 // tile kt complete (only group kt+1 pending)
        __syncthreads();             // publish tile kt; all warps done compute kt-1
        if (kt + 2 < nk) issue(kt + 2, (kt + 2) % 3);
        else cpa_commit();           // uniform group count

        uint32_t ab = base + (kt % 3) * GSTAGE;
        uint32_t bb = ab + GT_BYTES;

#pragma unroll
        for (int ks = 0; ks < 4; ks++) {
            uint32_t af[2][4];
#pragma unroll
            for (int mt = 0; mt < 2; mt++) {
                int r = wm * 32 + mt * 16 + a_r;
                uint32_t addr = ab + r * 128 + (((ks * 2 + a_hi) ^ (r & 7)) << 4);
                ldsm4(af[mt][0], af[mt][1], af[mt][2], af[mt][3], addr);
            }
#pragma unroll
            for (int nq = 0; nq < 4; nq++) {
                int n = wn * 64 + nq * 16 + b_r;
                uint32_t addr = bb + n * 128 + (((ks * 2 + b_hi) ^ (n & 7)) << 4);
                uint32_t b0, b1, b2, b3;
                ldsm4(b0, b1, b2, b3, addr);
                uint32_t bfa[2] = {b0, b1}, bfb[2] = {b2, b3};
#pragma unroll
                for (int mt = 0; mt < 2; mt++) {
                    mma_f16(acc[mt][2 * nq], af[mt], bfa);
                    mma_f16(acc[mt][2 * nq + 1], af[mt], bfb);
                }
            }
        }
        // no end-of-loop barrier: next iter's top barrier orders buffer reuse
    }
    cpa_wait_all();

#pragma unroll
    for (int mt = 0; mt < 2; mt++) {
        int row = bm + wm * 32 + mt * 16 + g;
#pragma unroll
        for (int nt = 0; nt < 8; nt++) {
            int col = bn + wn * 64 + nt * 8 + tig * 2;
            float bx = bias[col], by = bias[col + 1];
            float2 o0 = make_float2(acc[mt][nt][0] + bx, acc[mt][nt][1] + by);
            float2 o1 = make_float2(acc[mt][nt][2] + bx, acc[mt][nt][3] + by);
            *(float2*)(C + (size_t)row * N + col) = o0;
            *(float2*)(C + (size_t)(row + 8) * N + col) = o1;
        }
    }
}

// ---------------------------------------------------------------------------
// RoPE (reference's scrambled indexing). q is pre-scaled by 0.125*log2(e)
// so flash softmax can run in the exp2 domain.
// ---------------------------------------------------------------------------
__device__ __forceinline__ float invfreq(int i) {
    return exp2f(-(float)i * (13.287712379549449f / 32.0f));
}
__device__ __forceinline__ float rope_val(float tf, int i) {
    if (i < 32) return sinf(tf * invfreq(i));
    return cosf(tf * invfreq(i - 32));
}

__global__ void rope_kernel()
{
    int idx = blockIdx.x * blockDim.x + threadIdx.x;
    int h = idx % NHEAD;
    int t = (idx / NHEAD) % T_SEQ;
    int b = idx / (NHEAD * T_SEQ);
    float tf = (float)t;

    float sv[32], cv[32];
#pragma unroll
    for (int j = 0; j < 32; j++) {
        sv[j] = rope_val(tf, 2 * j);
        cv[j] = rope_val(tf, 2 * j + 1);
    }

    size_t off = ((size_t)(b * T_SEQ + t)) * (3 * DMODEL) + h * HDIM;
    const float* base = g_qkv + off;
    __half* hbase = g_qkvh + off;

#pragma unroll
    for (int s = 0; s < 2; s++) {            // q (s=0, scaled), k (s=1)
        const float* p = base + s * DMODEL;
        __half* ph = hbase + s * DMODEL;
        float sc = (s == 0) ? 0.125f * 1.4426950408889634f : 1.0f;
        float x[64];
#pragma unroll
        for (int d = 0; d < 64; d += 4) {
            float4 v = *(const float4*)(p + d);
            x[d] = v.x; x[d + 1] = v.y; x[d + 2] = v.z; x[d + 3] = v.w;
        }
        float o[64];
#pragma unroll
        for (int j = 0; j < 32; j++) {
            o[j]      = (x[2 * j] * cv[j] - x[2 * j + 1] * sv[j]) * sc;
            o[32 + j] = (x[2 * j] * sv[j] + x[2 * j + 1] * cv[j]) * sc;
        }
#pragma unroll
        for (int d = 0; d < 64; d += 4) {
            __half2 h0 = __floats2half2_rn(o[d], o[d + 1]);
            __half2 h1 = __floats2half2_rn(o[d + 2], o[d + 3]);
            uint2 u = make_uint2(h2u(h0), h2u(h1));
            *(uint2*)(ph + d) = u;
        }
    }
    const float* pv = base + 2 * DMODEL;
    __half* pvh = hbase + 2 * DMODEL;
#pragma unroll
    for (int d = 0; d < 64; d += 4) {
        float4 v = *(const float4*)(pv + d);
        __half2 h0 = __floats2half2_rn(v.x, v.y);
        __half2 h1 = __floats2half2_rn(v.z, v.w);
        uint2 u = make_uint2(h2u(h0), h2u(h1));
        *(uint2*)(pvh + d) = u;
    }
}

// ---------------------------------------------------------------------------
// Flash attention, fp16 mma, exp2-domain softmax, 3-stage cp.async pipeline,
// ONE barrier per key-tile (wait1 -> barrier -> issue -> compute).
// ---------------------------------------------------------------------------
#define FT_BYTES (64 * 64 * 2)           // 8192 per tile (K or V)
#define FSTAGE   (2 * FT_BYTES)          // 16384
#define FLASH_SMEM (3 * FSTAGE)          // 49152

__global__ __launch_bounds__(128) void flash_h16()
{
    extern __shared__ __half fsm[];

    int qt = (gridDim.x - 1) - blockIdx.x;
    int h = blockIdx.y, b = blockIdx.z;
    int tid = threadIdx.x, warp = tid >> 5, lane = tid & 31;
    int g = lane >> 2, tig = lane & 3;
    int q0 = qt * 64 + warp * 16;

    uint32_t base = (uint32_t)__cvta_generic_to_shared(fsm);

    auto issue = [&](int ktile, int buf) {   // ktile = 64-key tile index
        int k0 = ktile * 64;
        uint32_t kb = base + buf * FSTAGE;
        uint32_t vb = kb + FT_BYTES;
#pragma unroll
        for (int i = 0; i < 4; i++) {
            int c = tid + i * 128;              // 0..511
            int row = c >> 3, cc = c & 7;
            uint32_t sw = (uint32_t)(row * 128 + ((cc ^ (row & 7)) << 4));
            const __half* kg = g_qkvh + ((size_t)(b * T_SEQ + k0 + row)) * 3072
                               + 1024 + h * 64 + cc * 8;
            cpa16(kb + sw, kg);
            cpa16(vb + sw, kg + 1024);
        }
        cpa_commit();
    };

    // Q fragments (pre-scaled by 0.125*log2e in rope)
    uint32_t qf[4][4];
    {
        const __half* qb = g_qkvh + ((size_t)(b * T_SEQ + q0)) * 3072 + h * 64;
        const __half* r0 = qb + (size_t)g * 3072;
        const __half* r1 = qb + (size_t)(g + 8) * 3072;
#pragma unroll
        for (int ks = 0; ks < 4; ks++) {
            qf[ks][0] = *(const uint32_t*)(r0 + ks * 16 + 2 * tig);
            qf[ks][1] = *(const uint32_t*)(r1 + ks * 16 + 2 * tig);
            qf[ks][2] = *(const uint32_t*)(r0 + ks * 16 + 8 + 2 * tig);
            qf[ks][3] = *(const uint32_t*)(r1 + ks * 16 + 8 + 2 * tig);
        }
    }

    float oacc[8][4];
#pragma unroll
    for (int i = 0; i < 8; i++)
#pragma unroll
        for (int e = 0; e < 4; e++) oacc[i][e] = 0.f;
    float m0 = -INFINITY, m1 = -INFINITY, l0 = 0.f, l1 = 0.f;

    // ldmatrix lane offsets
    int kb_r = (lane & 7) + ((lane >> 4) & 1) * 8;
    int kb_hi = (lane >> 3) & 1;
    int vt_r = (lane & 7) + ((lane >> 3) & 1) * 8;
    int vt_hi = (lane >> 4) & 1;

    int ntiles = qt + 1;
    issue(0, 0);
    issue(1, 1);        // tile index 1; unused if qt==0, in-bounds

    for (int kt = 0; kt < ntiles; kt++) {
        int k0 = kt * 64;
        cpa_wait1();
        __syncthreads();
        if (kt + 2 < ntiles) issue(kt + 2, (kt + 2) % 3);
        else cpa_commit();

        uint32_t kb = base + (kt % 3) * FSTAGE;
        uint32_t vb = kb + FT_BYTES;

        // ---- S = Q K^T (16q x 64keys per warp), log2-domain scores
        float sacc[8][4];
#pragma unroll
        for (int nt = 0; nt < 8; nt++)
#pragma unroll
            for (int e = 0; e < 4; e++) sacc[nt][e] = 0.f;
#pragma unroll
        for (int ks = 0; ks < 4; ks++) {
#pragma unroll
            for (int nq = 0; nq < 4; nq++) {
                int n = nq * 16 + kb_r;
                uint32_t addr = kb + n * 128 + (((ks * 2 + kb_hi) ^ (n & 7)) << 4);
                uint32_t b0, b1, b2, b3;
                ldsm4(b0, b1, b2, b3, addr);
                uint32_t bfa[2] = {b0, b1}, bfb[2] = {b2, b3};
                mma_f16(sacc[2 * nq], qf[ks], bfa);
                mma_f16(sacc[2 * nq + 1], qf[ks], bfb);
            }
        }

        // ---- causal mask (diagonal block only)
        if (kt == qt) {
#pragma unroll
            for (int nt = 0; nt < 8; nt++) {
                int key = k0 + nt * 8 + 2 * tig;
                if (key     > q0 + g)     sacc[nt][0] = -INFINITY;
                if (key + 1 > q0 + g)     sacc[nt][1] = -INFINITY;
                if (key     > q0 + 8 + g) sacc[nt][2] = -INFINITY;
                if (key + 1 > q0 + 8 + g) sacc[nt][3] = -INFINITY;
            }
        }

        // ---- online softmax (exp2 domain)
        float mx0 = -INFINITY, mx1 = -INFINITY;
#pragma unroll
        for (int nt = 0; nt < 8; nt++) {
            mx0 = fmaxf(mx0, fmaxf(sacc[nt][0], sacc[nt][1]));
            mx1 = fmaxf(mx1, fmaxf(sacc[nt][2], sacc[nt][3]));
        }
        mx0 = fmaxf(mx0, __shfl_xor_sync(0xffffffffu, mx0, 1));
        mx0 = fmaxf(mx0, __shfl_xor_sync(0xffffffffu, mx0, 2));
        mx1 = fmaxf(mx1, __shfl_xor_sync(0xffffffffu, mx1, 1));
        mx1 = fmaxf(mx1, __shfl_xor_sync(0xffffffffu, mx1, 2));

        float mn0 = fmaxf(m0, mx0), mn1 = fmaxf(m1, mx1);
        float a0 = ex2(m0 - mn0), a1 = ex2(m1 - mn1);
        m0 = mn0; m1 = mn1;
        l0 *= a0; l1 *= a1;
#pragma unroll
        for (int nd = 0; nd < 8; nd++) {
            oacc[nd][0] *= a0; oacc[nd][1] *= a0;
            oacc[nd][2] *= a1; oacc[nd][3] *= a1;
        }

        // ---- P = exp2(S - m) in registers
        uint32_t pf[8][2];
#pragma unroll
        for (int nt = 0; nt < 8; nt++) {
            float p0 = ex2(sacc[nt][0] - mn0);
            float p1 = ex2(sacc[nt][1] - mn0);
            float p2 = ex2(sacc[nt][2] - mn1);
            float p3 = ex2(sacc[nt][3] - mn1);
            l0 += p0 + p1; l1 += p2 + p3;
            pf[nt][0] = h2u(__floats2half2_rn(p0, p1));
            pf[nt][1] = h2u(__floats2half2_rn(p2, p3));
        }

        // ---- O += P V
#pragma unroll
        for (int kk = 0; kk < 4; kk++) {
            uint32_t af[4] = {pf[2 * kk][0], pf[2 * kk][1],
                              pf[2 * kk + 1][0], pf[2 * kk + 1][1]};
#pragma unroll
            for (int dq = 0; dq < 4; dq++) {
                int key = kk * 16 + vt_r;
                uint32_t addr = vb + key * 128 + (((dq * 2 + vt_hi) ^ (key & 7)) << 4);
                uint32_t b0, b1, b2, b3;
                ldsm4t(b0, b1, b2, b3, addr);
                uint32_t bfa[2] = {b0, b1}, bfb[2] = {b2, b3};
                mma_f16(oacc[2 * dq], af, bfa);
                mma_f16(oacc[2 * dq + 1], af, bfb);
            }
        }
        // no end-of-loop barrier (next iter's top barrier orders reuse)
    }
    cpa_wait_all();

    l0 += __shfl_xor_sync(0xffffffffu, l0, 1);
    l0 += __shfl_xor_sync(0xffffffffu, l0, 2);
    l1 += __shfl_xor_sync(0xffffffffu, l1, 1);
    l1 += __shfl_xor_sync(0xffffffffu, l1, 2);
    float i0 = 1.f / l0, i1 = 1.f / l1;

    __half* ob = g_attnh + ((size_t)(b * T_SEQ + q0)) * 1024 + h * 64;
#pragma unroll
    for (int nd = 0; nd < 8; nd++) {
        int col = nd * 8 + 2 * tig;
        __half2 o0 = __floats2half2_rn(oacc[nd][0] * i0, oacc[nd][1] * i0);
        __half2 o1 = __floats2half2_rn(oacc[nd][2] * i1, oacc[nd][3] * i1);
        *(uint32_t*)(ob + (size_t)g * 1024 + col) = h2u(o0);
        *(uint32_t*)(ob + (size_t)(g + 8) * 1024 + col) = h2u(o1);
    }
}

// ---------------------------------------------------------------------------
extern "C" void kernel_launch(void* const* d_in, const int* in_sizes, int n_in,
                              void* d_out, int out_size)
{
    const float* x      = (const float*)d_in[0];
    const float* qkv_w  = (const float*)d_in[1];
    const float* qkv_b  = (const float*)d_in[2];
    const float* out_w  = (const float*)d_in[3];
    const float* out_b  = (const float*)d_in[4];
    float* out = (float*)d_out;

    float* qkv_buf;
    __half *xh, *wth, *owth, *attnh;
    cudaGetSymbolAddress((void**)&qkv_buf, g_qkv);
    cudaGetSymbolAddress((void**)&xh, g_xh);
    cudaGetSymbolAddress((void**)&wth, g_wth);
    cudaGetSymbolAddress((void**)&owth, g_owth);
    cudaGetSymbolAddress((void**)&attnh, g_attnh);

    const int M = BATCH * T_SEQ;   // 4096

    cudaFuncSetAttribute(gemm_h, cudaFuncAttributeMaxDynamicSharedMemorySize,
                         GEMM_SMEM);
    cudaFuncSetAttribute(flash_h16, cudaFuncAttributeMaxDynamicSharedMemorySize,
                         FLASH_SMEM);

    // 0) convert x to half; transpose weights to [N,K] half
    conv_half<<<(M * DMODEL / 4 + 255) / 256, 256>>>(x, xh, M * DMODEL / 4);
    transpose_half<<<dim3(3 * DMODEL / 32, DMODEL / 32), dim3(32, 8)>>>(
        qkv_w, wth, DMODEL, 3 * DMODEL);
    transpose_half<<<dim3(DMODEL / 32, DMODEL / 32), dim3(32, 8)>>>(
        out_w, owth, DMODEL, DMODEL);

    // 1) QKV GEMM + bias (fp16 tensor, fp32 out)
    gemm_h<<<dim3(3 * DMODEL / 128, M / 128), 256, GEMM_SMEM>>>(
        xh, wth, qkv_b, qkv_buf, M, 3 * DMODEL, DMODEL);

    // 2) RoPE -> half q(scaled)/k/v
    rope_kernel<<<(BATCH * T_SEQ * NHEAD) / 256, 256>>>();

    // 3) Flash attention (fp16, exp2 softmax) -> g_attnh
    flash_h16<<<dim3(T_SEQ / 64, NHEAD, BATCH), 128, FLASH_SMEM>>>();

    // 4) Output GEMM + bias
    gemm_h<<<dim3(DMODEL / 128, M / 128), 256, GEMM_SMEM>>>(
        attnh, owth, out_b, out, M, DMODEL, DMODEL);
}

// round 12
// speedup vs baseline: 8.8144x; 1.0152x over previous
#include <cuda_runtime.h>
#include <cuda_fp16.h>
#include <math.h>
#include <stdint.h>

#define T_SEQ 2048
#define BATCH 2
#define NHEAD 16
#define HDIM 64
#define DMODEL 1024

__device__ float  g_qkv[BATCH * T_SEQ * 3 * DMODEL];    // fp32 GEMM output
__device__ __half g_qkvh[BATCH * T_SEQ * 3 * DMODEL];   // half q(scaled,rot), k(rot), v
__device__ __half g_attnh[BATCH * T_SEQ * DMODEL];      // flash output, half
__device__ __half g_xh[BATCH * T_SEQ * DMODEL];         // x as half
__device__ __half g_wth[3 * DMODEL * DMODEL];           // qkv_w^T [3D, D] half
__device__ __half g_owth[DMODEL * DMODEL];              // out_w^T [D, D] half

// ---------------------------------------------------------------------------
__device__ __forceinline__ void mma_f16(float* d, const uint32_t* a, const uint32_t* b) {
    asm volatile(
        "mma.sync.aligned.m16n8k16.row.col.f32.f16.f16.f32 "
        "{%0,%1,%2,%3}, {%4,%5,%6,%7}, {%8,%9}, {%0,%1,%2,%3};"
        : "+f"(d[0]), "+f"(d[1]), "+f"(d[2]), "+f"(d[3])
        : "r"(a[0]), "r"(a[1]), "r"(a[2]), "r"(a[3]), "r"(b[0]), "r"(b[1]));
}

__device__ __forceinline__ void ldsm4(uint32_t& r0, uint32_t& r1, uint32_t& r2,
                                      uint32_t& r3, uint32_t a) {
    asm volatile("ldmatrix.sync.aligned.m8n8.x4.shared.b16 {%0,%1,%2,%3}, [%4];"
                 : "=r"(r0), "=r"(r1), "=r"(r2), "=r"(r3) : "r"(a));
}
__device__ __forceinline__ void ldsm4t(uint32_t& r0, uint32_t& r1, uint32_t& r2,
                                       uint32_t& r3, uint32_t a) {
    asm volatile("ldmatrix.sync.aligned.m8n8.x4.trans.shared.b16 {%0,%1,%2,%3}, [%4];"
                 : "=r"(r0), "=r"(r1), "=r"(r2), "=r"(r3) : "r"(a));
}

__device__ __forceinline__ void cpa16(uint32_t saddr, const void* g) {
    asm volatile("cp.async.cg.shared.global [%0], [%1], 16;" :: "r"(saddr), "l"(g));
}
__device__ __forceinline__ void cpa_commit() {
    asm volatile("cp.async.commit_group;");
}
__device__ __forceinline__ void cpa_wait1() {
    asm volatile("cp.async.wait_group 1;" ::: "memory");
}
__device__ __forceinline__ void cpa_wait_all() {
    asm volatile("cp.async.wait_all;" ::: "memory");
}

__device__ __forceinline__ uint32_t h2u(__half2 h) {
    return *reinterpret_cast<uint32_t*>(&h);
}

__device__ __forceinline__ float ex2(float x) {
    float y;
    asm("ex2.approx.f32 %0, %1;" : "=f"(y) : "f"(x));
    return y;
}

// exp2 of a packed half2 (one MUFU op for two values)
__device__ __forceinline__ uint32_t ex2_h2(uint32_t x) {
    uint32_t y;
    asm("ex2.approx.f16x2 %0, %1;" : "=r"(y) : "r"(x));
    return y;
}

// ---------------------------------------------------------------------------
// Pre-passes.
// ---------------------------------------------------------------------------
__global__ void conv_half(const float* __restrict__ src, __half* __restrict__ dst, int n4)
{
    int i = blockIdx.x * blockDim.x + threadIdx.x;
    if (i < n4) {
        float4 v = ((const float4*)src)[i];
        __half2 a = __floats2half2_rn(v.x, v.y);
        __half2 b = __floats2half2_rn(v.z, v.w);
        uint2 o = make_uint2(h2u(a), h2u(b));
        ((uint2*)dst)[i] = o;
    }
}

// src [R][C] fp32 row-major -> dst [C][R] half row-major.
__global__ void transpose_half(const float* __restrict__ src, __half* __restrict__ dst,
                               int R, int C)
{
    __shared__ float tile[32][33];
    int c0 = blockIdx.x * 32, r0 = blockIdx.y * 32;
    int x = threadIdx.x, y = threadIdx.y;   // block (32, 8)
#pragma unroll
    for (int i = 0; i < 32; i += 8)
        tile[y + i][x] = src[(size_t)(r0 + y + i) * C + c0 + x];
    __syncthreads();
#pragma unroll
    for (int i = 0; i < 32; i += 8)
        dst[(size_t)(c0 + y + i) * R + r0 + x] = __float2half_rn(tile[x][y + i]);
}

// ---------------------------------------------------------------------------
// fp16 tensor GEMM: C[M,N] = A[M,K] * Bt[N,K]^T + bias.  (unchanged from R11)
// ---------------------------------------------------------------------------
#define GT_BYTES (128 * 64 * 2)          // 16384 per tile
#define GSTAGE   (2 * GT_BYTES)          // A + B = 32768
#define GEMM_SMEM (3 * GSTAGE)           // 98304

__global__ __launch_bounds__(256, 2) void gemm_h(
    const __half* __restrict__ A, const __half* __restrict__ Bt,
    const float* __restrict__ bias, float* __restrict__ C,
    int M, int N, int K)
{
    extern __shared__ __half hsm[];

    int tid = threadIdx.x;
    int lane = tid & 31, warp = tid >> 5;
    int g = lane >> 2, tig = lane & 3;
    int bm = blockIdx.y * 128, bn = blockIdx.x * 128;
    int wm = warp & 3, wn = warp >> 2;

    float acc[2][8][4];
#pragma unroll
    for (int i = 0; i < 2; i++)
#pragma unroll
        for (int j = 0; j < 8; j++)
#pragma unroll
            for (int e = 0; e < 4; e++) acc[i][j][e] = 0.f;

    uint32_t base = (uint32_t)__cvta_generic_to_shared(hsm);

    auto issue = [&](int kc, int buf) {   // kc = K-tile index
        uint32_t ab = base + buf * GSTAGE;
        uint32_t bb = ab + GT_BYTES;
#pragma unroll
        for (int i = 0; i < 4; i++) {
            int c = tid + i * 256;              // 0..1023
            int row = c >> 3, cc = c & 7;
            uint32_t sw = (uint32_t)(row * 128 + ((cc ^ (row & 7)) << 4));
            cpa16(ab + sw, A + (size_t)(bm + row) * K + kc * 64 + cc * 8);
            cpa16(bb + sw, Bt + (size_t)(bn + row) * K + kc * 64 + cc * 8);
        }
        cpa_commit();
    };

    int nk = K / 64;
    issue(0, 0);
    issue(1, 1);

    int a_r = (lane & 7) + ((lane >> 3) & 1) * 8;
    int a_hi = (lane >> 4) & 1;
    int b_r = (lane & 7) + ((lane >> 4) & 1) * 8;
    int b_hi = (lane >> 3) & 1;

    for (int kt = 0; kt < nk; kt++) {
        cpa_wait1();
        __syncthreads();
        if (kt + 2 < nk) issue(kt + 2, (kt + 2) % 3);
        else cpa_commit();

        uint32_t ab = base + (kt % 3) * GSTAGE;
        uint32_t bb = ab + GT_BYTES;

#pragma unroll
        for (int ks = 0; ks < 4; ks++) {
            uint32_t af[2][4];
#pragma unroll
            for (int mt = 0; mt < 2; mt++) {
                int r = wm * 32 + mt * 16 + a_r;
                uint32_t addr = ab + r * 128 + (((ks * 2 + a_hi) ^ (r & 7)) << 4);
                ldsm4(af[mt][0], af[mt][1], af[mt][2], af[mt][3], addr);
            }
#pragma unroll
            for (int nq = 0; nq < 4; nq++) {
                int n = wn * 64 + nq * 16 + b_r;
                uint32_t addr = bb + n * 128 + (((ks * 2 + b_hi) ^ (n & 7)) << 4);
                uint32_t b0, b1, b2, b3;
                ldsm4(b0, b1, b2, b3, addr);
                uint32_t bfa[2] = {b0, b1}, bfb[2] = {b2, b3};
#pragma unroll
                for (int mt = 0; mt < 2; mt++) {
                    mma_f16(acc[mt][2 * nq], af[mt], bfa);
                    mma_f16(acc[mt][2 * nq + 1], af[mt], bfb);
                }
            }
        }
    }
    cpa_wait_all();

#pragma unroll
    for (int mt = 0; mt < 2; mt++) {
        int row = bm + wm * 32 + mt * 16 + g;
#pragma unroll
        for (int nt = 0; nt < 8; nt++) {
            int col = bn + wn * 64 + nt * 8 + tig * 2;
            float bx = bias[col], by = bias[col + 1];
            float2 o0 = make_float2(acc[mt][nt][0] + bx, acc[mt][nt][1] + by);
            float2 o1 = make_float2(acc[mt][nt][2] + bx, acc[mt][nt][3] + by);
            *(float2*)(C + (size_t)row * N + col) = o0;
            *(float2*)(C + (size_t)(row + 8) * N + col) = o1;
        }
    }
}

// ---------------------------------------------------------------------------
// RoPE (reference's scrambled indexing). q pre-scaled by 0.125*log2(e).
// ---------------------------------------------------------------------------
__device__ __forceinline__ float invfreq(int i) {
    return exp2f(-(float)i * (13.287712379549449f / 32.0f));
}
__device__ __forceinline__ float rope_val(float tf, int i) {
    if (i < 32) return sinf(tf * invfreq(i));
    return cosf(tf * invfreq(i - 32));
}

__global__ void rope_kernel()
{
    int idx = blockIdx.x * blockDim.x + threadIdx.x;
    int h = idx % NHEAD;
    int t = (idx / NHEAD) % T_SEQ;
    int b = idx / (NHEAD * T_SEQ);
    float tf = (float)t;

    float sv[32], cv[32];
#pragma unroll
    for (int j = 0; j < 32; j++) {
        sv[j] = rope_val(tf, 2 * j);
        cv[j] = rope_val(tf, 2 * j + 1);
    }

    size_t off = ((size_t)(b * T_SEQ + t)) * (3 * DMODEL) + h * HDIM;
    const float* base = g_qkv + off;
    __half* hbase = g_qkvh + off;

#pragma unroll
    for (int s = 0; s < 2; s++) {            // q (s=0, scaled), k (s=1)
        const float* p = base + s * DMODEL;
        __half* ph = hbase + s * DMODEL;
        float sc = (s == 0) ? 0.125f * 1.4426950408889634f : 1.0f;
        float x[64];
#pragma unroll
        for (int d = 0; d < 64; d += 4) {
            float4 v = *(const float4*)(p + d);
            x[d] = v.x; x[d + 1] = v.y; x[d + 2] = v.z; x[d + 3] = v.w;
        }
        float o[64];
#pragma unroll
        for (int j = 0; j < 32; j++) {
            o[j]      = (x[2 * j] * cv[j] - x[2 * j + 1] * sv[j]) * sc;
            o[32 + j] = (x[2 * j] * sv[j] + x[2 * j + 1] * cv[j]) * sc;
        }
#pragma unroll
        for (int d = 0; d < 64; d += 4) {
            __half2 h0 = __floats2half2_rn(o[d], o[d + 1]);
            __half2 h1 = __floats2half2_rn(o[d + 2], o[d + 3]);
            uint2 u = make_uint2(h2u(h0), h2u(h1));
            *(uint2*)(ph + d) = u;
        }
    }
    const float* pv = base + 2 * DMODEL;
    __half* pvh = hbase + 2 * DMODEL;
#pragma unroll
    for (int d = 0; d < 64; d += 4) {
        float4 v = *(const float4*)(pv + d);
        __half2 h0 = __floats2half2_rn(v.x, v.y);
        __half2 h1 = __floats2half2_rn(v.z, v.w);
        uint2 u = make_uint2(h2u(h0), h2u(h1));
        *(uint2*)(pvh + d) = u;
    }
}

// ---------------------------------------------------------------------------
// Flash attention, fp16 mma, slim softmax:
//  - P = ex2.approx.f16x2 on half-packed (s - m)  (MUFU per tile 34 -> 18)
//  - row-sum l via mma with ones-B (kills 32 FADD/tile + final shfl tree)
// 3-stage cp.async pipeline, one barrier per key-tile.
// ---------------------------------------------------------------------------
#define FT_BYTES (64 * 64 * 2)           // 8192 per tile (K or V)
#define FSTAGE   (2 * FT_BYTES)          // 16384
#define FLASH_SMEM (3 * FSTAGE)          // 49152

__global__ __launch_bounds__(128) void flash_h16()
{
    extern __shared__ __half fsm[];

    int qt = (gridDim.x - 1) - blockIdx.x;
    int h = blockIdx.y, b = blockIdx.z;
    int tid = threadIdx.x, warp = tid >> 5, lane = tid & 31;
    int g = lane >> 2, tig = lane & 3;
    int q0 = qt * 64 + warp * 16;

    uint32_t base = (uint32_t)__cvta_generic_to_shared(fsm);

    auto issue = [&](int ktile, int buf) {   // ktile = 64-key tile index
        int k0 = ktile * 64;
        uint32_t kb = base + buf * FSTAGE;
        uint32_t vb = kb + FT_BYTES;
#pragma unroll
        for (int i = 0; i < 4; i++) {
            int c = tid + i * 128;              // 0..511
            int row = c >> 3, cc = c & 7;
            uint32_t sw = (uint32_t)(row * 128 + ((cc ^ (row & 7)) << 4));
            const __half* kg = g_qkvh + ((size_t)(b * T_SEQ + k0 + row)) * 3072
                               + 1024 + h * 64 + cc * 8;
            cpa16(kb + sw, kg);
            cpa16(vb + sw, kg + 1024);
        }
        cpa_commit();
    };

    // Q fragments (pre-scaled by 0.125*log2e in rope)
    uint32_t qf[4][4];
    {
        const __half* qb = g_qkvh + ((size_t)(b * T_SEQ + q0)) * 3072 + h * 64;
        const __half* r0 = qb + (size_t)g * 3072;
        const __half* r1 = qb + (size_t)(g + 8) * 3072;
#pragma unroll
        for (int ks = 0; ks < 4; ks++) {
            qf[ks][0] = *(const uint32_t*)(r0 + ks * 16 + 2 * tig);
            qf[ks][1] = *(const uint32_t*)(r1 + ks * 16 + 2 * tig);
            qf[ks][2] = *(const uint32_t*)(r0 + ks * 16 + 8 + 2 * tig);
            qf[ks][3] = *(const uint32_t*)(r1 + ks * 16 + 8 + 2 * tig);
        }
    }

    float oacc[8][4];
#pragma unroll
    for (int i = 0; i < 8; i++)
#pragma unroll
        for (int e = 0; e < 4; e++) oacc[i][e] = 0.f;
    float lacc[4] = {0.f, 0.f, 0.f, 0.f};        // rowsum via ones-mma
    float m0 = -INFINITY, m1 = -INFINITY;

    const uint32_t ONES2 = 0x3C003C00u;          // half2(1, 1)
    uint32_t onesb[2] = {ONES2, ONES2};

    // ldmatrix lane offsets
    int kb_r = (lane & 7) + ((lane >> 4) & 1) * 8;
    int kb_hi = (lane >> 3) & 1;
    int vt_r = (lane & 7) + ((lane >> 3) & 1) * 8;
    int vt_hi = (lane >> 4) & 1;

    int ntiles = qt + 1;
    issue(0, 0);
    issue(1, 1);        // tile index 1; unused if qt==0, in-bounds

    for (int kt = 0; kt < ntiles; kt++) {
        int k0 = kt * 64;
        cpa_wait1();
        __syncthreads();
        if (kt + 2 < ntiles) issue(kt + 2, (kt + 2) % 3);
        else cpa_commit();

        uint32_t kb = base + (kt % 3) * FSTAGE;
        uint32_t vb = kb + FT_BYTES;

        // ---- S = Q K^T (16q x 64keys per warp), log2-domain scores
        float sacc[8][4];
#pragma unroll
        for (int nt = 0; nt < 8; nt++)
#pragma unroll
            for (int e = 0; e < 4; e++) sacc[nt][e] = 0.f;
#pragma unroll
        for (int ks = 0; ks < 4; ks++) {
#pragma unroll
            for (int nq = 0; nq < 4; nq++) {
                int n = nq * 16 + kb_r;
                uint32_t addr = kb + n * 128 + (((ks * 2 + kb_hi) ^ (n & 7)) << 4);
                uint32_t b0, b1, b2, b3;
                ldsm4(b0, b1, b2, b3, addr);
                uint32_t bfa[2] = {b0, b1}, bfb[2] = {b2, b3};
                mma_f16(sacc[2 * nq], qf[ks], bfa);
                mma_f16(sacc[2 * nq + 1], qf[ks], bfb);
            }
        }

        // ---- causal mask (diagonal block only)
        if (kt == qt) {
#pragma unroll
            for (int nt = 0; nt < 8; nt++) {
                int key = k0 + nt * 8 + 2 * tig;
                if (key     > q0 + g)     sacc[nt][0] = -INFINITY;
                if (key + 1 > q0 + g)     sacc[nt][1] = -INFINITY;
                if (key     > q0 + 8 + g) sacc[nt][2] = -INFINITY;
                if (key + 1 > q0 + 8 + g) sacc[nt][3] = -INFINITY;
            }
        }

        // ---- online softmax (exp2 domain)
        float mx0 = -INFINITY, mx1 = -INFINITY;
#pragma unroll
        for (int nt = 0; nt < 8; nt++) {
            mx0 = fmaxf(mx0, fmaxf(sacc[nt][0], sacc[nt][1]));
            mx1 = fmaxf(mx1, fmaxf(sacc[nt][2], sacc[nt][3]));
        }
        mx0 = fmaxf(mx0, __shfl_xor_sync(0xffffffffu, mx0, 1));
        mx0 = fmaxf(mx0, __shfl_xor_sync(0xffffffffu, mx0, 2));
        mx1 = fmaxf(mx1, __shfl_xor_sync(0xffffffffu, mx1, 1));
        mx1 = fmaxf(mx1, __shfl_xor_sync(0xffffffffu, mx1, 2));

        float mn0 = fmaxf(m0, mx0), mn1 = fmaxf(m1, mx1);
        float a0 = ex2(m0 - mn0), a1 = ex2(m1 - mn1);
        m0 = mn0; m1 = mn1;
        lacc[0] *= a0; lacc[1] *= a0; lacc[2] *= a1; lacc[3] *= a1;
#pragma unroll
        for (int nd = 0; nd < 8; nd++) {
            oacc[nd][0] *= a0; oacc[nd][1] *= a0;
            oacc[nd][2] *= a1; oacc[nd][3] *= a1;
        }

        // ---- P = exp2(S - m) directly in half2 (ex2.approx.f16x2)
        uint32_t pf[8][2];
#pragma unroll
        for (int nt = 0; nt < 8; nt++) {
            __half2 d01 = __floats2half2_rn(sacc[nt][0] - mn0, sacc[nt][1] - mn0);
            __half2 d23 = __floats2half2_rn(sacc[nt][2] - mn1, sacc[nt][3] - mn1);
            pf[nt][0] = ex2_h2(h2u(d01));
            pf[nt][1] = ex2_h2(h2u(d23));
        }

        // ---- O += P V ; l += P 1  (rowsum in tensor core)
#pragma unroll
        for (int kk = 0; kk < 4; kk++) {
            uint32_t af[4] = {pf[2 * kk][0], pf[2 * kk][1],
                              pf[2 * kk + 1][0], pf[2 * kk + 1][1]};
            mma_f16(lacc, af, onesb);
#pragma unroll
            for (int dq = 0; dq < 4; dq++) {
                int key = kk * 16 + vt_r;
                uint32_t addr = vb + key * 128 + (((dq * 2 + vt_hi) ^ (key & 7)) << 4);
                uint32_t b0, b1, b2, b3;
                ldsm4t(b0, b1, b2, b3, addr);
                uint32_t bfa[2] = {b0, b1}, bfb[2] = {b2, b3};
                mma_f16(oacc[2 * dq], af, bfa);
                mma_f16(oacc[2 * dq + 1], af, bfb);
            }
        }
        // no end-of-loop barrier (next iter's top barrier orders reuse)
    }
    cpa_wait_all();

    // lacc[0] = rowsum(row g), lacc[2] = rowsum(row g+8) — no shfl needed
    float i0 = 1.f / lacc[0], i1 = 1.f / lacc[2];

    __half* ob = g_attnh + ((size_t)(b * T_SEQ + q0)) * 1024 + h * 64;
#pragma unroll
    for (int nd = 0; nd < 8; nd++) {
        int col = nd * 8 + 2 * tig;
        __half2 o0 = __floats2half2_rn(oacc[nd][0] * i0, oacc[nd][1] * i0);
        __half2 o1 = __floats2half2_rn(oacc[nd][2] * i1, oacc[nd][3] * i1);
        *(uint32_t*)(ob + (size_t)g * 1024 + col) = h2u(o0);
        *(uint32_t*)(ob + (size_t)(g + 8) * 1024 + col) = h2u(o1);
    }
}

// ---------------------------------------------------------------------------
extern "C" void kernel_launch(void* const* d_in, const int* in_sizes, int n_in,
                              void* d_out, int out_size)
{
    const float* x      = (const float*)d_in[0];
    const float* qkv_w  = (const float*)d_in[1];
    const float* qkv_b  = (const float*)d_in[2];
    const float* out_w  = (const float*)d_in[3];
    const float* out_b  = (const float*)d_in[4];
    float* out = (float*)d_out;

    float* qkv_buf;
    __half *xh, *wth, *owth, *attnh;
    cudaGetSymbolAddress((void**)&qkv_buf, g_qkv);
    cudaGetSymbolAddress((void**)&xh, g_xh);
    cudaGetSymbolAddress((void**)&wth, g_wth);
    cudaGetSymbolAddress((void**)&owth, g_owth);
    cudaGetSymbolAddress((void**)&attnh, g_attnh);

    const int M = BATCH * T_SEQ;   // 4096

    cudaFuncSetAttribute(gemm_h, cudaFuncAttributeMaxDynamicSharedMemorySize,
                         GEMM_SMEM);
    cudaFuncSetAttribute(flash_h16, cudaFuncAttributeMaxDynamicSharedMemorySize,
                         FLASH_SMEM);

    // 0) convert x to half; transpose weights to [N,K] half
    conv_half<<<(M * DMODEL / 4 + 255) / 256, 256>>>(x, xh, M * DMODEL / 4);
    transpose_half<<<dim3(3 * DMODEL / 32, DMODEL / 32), dim3(32, 8)>>>(
        qkv_w, wth, DMODEL, 3 * DMODEL);
    transpose_half<<<dim3(DMODEL / 32, DMODEL / 32), dim3(32, 8)>>>(
        out_w, owth, DMODEL, DMODEL);

    // 1) QKV GEMM + bias (fp16 tensor, fp32 out)
    gemm_h<<<dim3(3 * DMODEL / 128, M / 128), 256, GEMM_SMEM>>>(
        xh, wth, qkv_b, qkv_buf, M, 3 * DMODEL, DMODEL);

    // 2) RoPE -> half q(scaled)/k/v
    rope_kernel<<<(BATCH * T_SEQ * NHEAD) / 256, 256>>>();

    // 3) Flash attention (fp16, slim exp2 softmax) -> g_attnh
    flash_h16<<<dim3(T_SEQ / 64, NHEAD, BATCH), 128, FLASH_SMEM>>>();

    // 4) Output GEMM + bias
    gemm_h<<<dim3(DMODEL / 128, M / 128), 256, GEMM_SMEM>>>(
        attnh, owth, out_b, out, M, DMODEL, DMODEL);
}